// round 3
// baseline (speedup 1.0000x reference)
#include <cuda_runtime.h>
#include <cstdint>
#include <math.h>

#define H      1024
#define E      16
#define T      8192
#define TOPK   6
#define EPSV   1e-10f

// ---- GEMM tiling: block 128M x 256N, BK=16; warps 2x4, warptile 64x64 ----
#define BM 128
#define BN 256
#define BK 16
#define NCHUNK (H/BK)          // 64
#define BPADW  264             // B row stride in words (264 % 32 == 8 -> conflict-free)
#define ABYTES (128*16*4)      // 8192
#define BBYTES (16*BPADW*4)    // 16896
#define BUFB   (ABYTES+BBYTES) // 25088
#define DSMEM  (2*BUFB + 1024)

// ---- scratch (device globals; no allocation allowed) ----
__device__ int   d_counts[E];
__device__ int   d_perm_token[E*T];
__device__ int   d_perm_dest [E*T];
__device__ float d_perm_coef [E*T];
__device__ float d_bias[T];
__device__ float d_scratch[(size_t)T*TOPK*H];   // 192 MB

__device__ __forceinline__ unsigned f2tf(float f) {
    unsigned r;
    asm("cvt.rna.tf32.f32 %0, %1;" : "=r"(r) : "f"(f));
    return r;
}

// A smem word index: 128 rows x 16 words, 16B-slot swizzle within row:
// word(r,c) = r*16 + (((c>>2) ^ (r&3))<<2) + (c&3)
__device__ __forceinline__ int a_word(int r, int c) {
    return r * 16 + ((((c >> 2) ^ (r & 3)) << 2) | (c & 3));
}

// ============================================================
__global__ void zero_counts_kernel() {
    if (threadIdx.x < E) d_counts[threadIdx.x] = 0;
}

// ============================================================
// Router: warp per token (unchanged from R1; ~15us)
__global__ void __launch_bounds__(256) router_kernel(
    const float* __restrict__ tokens,
    const float* __restrict__ rw,
    const float* __restrict__ rb)
{
    const int warp = threadIdx.x >> 5;
    const int lane = threadIdx.x & 31;

    for (int it = 0; it < 16; ++it) {
        const int t = blockIdx.x * 128 + warp * 16 + it;

        float xr[32];
        const float* xp = tokens + (size_t)t * H;
        #pragma unroll
        for (int j = 0; j < 32; ++j) xr[j] = xp[j * 32 + lane];

        float myLogit = -INFINITY;
        #pragma unroll
        for (int e = 0; e < E; ++e) {
            const float* wp = rw + e * H;
            float s = 0.f;
            #pragma unroll
            for (int j = 0; j < 32; ++j) s += xr[j] * wp[j * 32 + lane];
            #pragma unroll
            for (int o = 16; o; o >>= 1) s += __shfl_xor_sync(0xffffffffu, s, o);
            if (lane == e) myLogit = s + rb[e];
        }

        float m = myLogit;
        #pragma unroll
        for (int o = 16; o; o >>= 1) m = fmaxf(m, __shfl_xor_sync(0xffffffffu, m, o));
        float p = (lane < E) ? expf(myLogit - m) : 0.f;
        float Z = p;
        #pragma unroll
        for (int o = 16; o; o >>= 1) Z += __shfl_xor_sync(0xffffffffu, Z, o);

        float pv[E];
        #pragma unroll
        for (int e = 0; e < E; ++e) pv[e] = __shfl_sync(0xffffffffu, p, e);

        if (lane == 0) {
            int   ids[TOPK];
            float ps [TOPK];
            float s = 0.f;
            #pragma unroll
            for (int k = 0; k < TOPK; ++k) {
                int best = 0; float bv = pv[0];
                #pragma unroll
                for (int e = 1; e < E; ++e)
                    if (pv[e] > bv) { bv = pv[e]; best = e; }
                ids[k] = best; ps[k] = bv; pv[best] = -1.f; s += bv;
            }
            #pragma unroll
            for (int k = 0; k < TOPK; ++k) {
                const float coef = ps[k] / s;
                const int e = ids[k];
                const int pos = atomicAdd(&d_counts[e], 1);
                d_perm_token[e * T + pos] = t;
                d_perm_dest [e * T + pos] = t * TOPK + k;
                d_perm_coef [e * T + pos] = coef;
            }
            const float sn = s / Z;
            d_bias[t] = EPSV * sn / (sn + EPSV);
        }
    }
}

// ============================================================
// Grouped GEMM, legacy mma.sync tf32, fp32 accum.
// Grid (H/BN=4, 64, 16) with early exit past each expert's count.
__global__ void __launch_bounds__(256, 1) moe_gemm_kernel(
    const float* __restrict__ x,
    const float* __restrict__ ew)
{
    const int e     = blockIdx.z;
    const int cnt   = d_counts[e];
    const int mBase = blockIdx.y * BM;
    if (mBase >= cnt) return;
    const int nBase = blockIdx.x * BN;

    const float* Wp   = ew + (size_t)e * H * H;     // [K=H, N=H] row-major
    const int*   ptok = d_perm_token + e * T;

    extern __shared__ char dsm[];
    // align to 1024B
    char* sb = dsm + ((1024 - (((uintptr_t)dsm) & 1023)) & 1023);

    const int tid  = threadIdx.x;
    const int lane = tid & 31;
    const int wid  = tid >> 5;
    const int wm   = wid >> 2;    // 0..1
    const int wn   = wid & 3;     // 0..3

    // ---- staging maps ----
    // A: thread -> (rows r0 = tid>>2 and r0+64, seg s = tid&3)
    //    4 lanes cover one 64B gathered row chunk -> 100% sectors
    const int a_s = tid & 3;
    const int a_r0 = tid >> 2;            // 0..63
    const float* a_gp[2];
    int a_w[2];
    #pragma unroll
    for (int i = 0; i < 2; ++i) {
        const int r  = a_r0 + 64 * i;
        const int gm = mBase + r;
        const int tok = ptok[(gm < cnt) ? gm : (cnt - 1)];
        a_gp[i] = x + (size_t)tok * H + a_s * 4;
        a_w [i] = a_word(r, a_s * 4);     // 4 consecutive words (one 16B slot)
    }
    // B: thread -> (k = tid>>6 + 4i, n4 = tid&63)
    const int b_n4 = tid & 63;
    const float* b_gp[4];
    int b_w[4];
    #pragma unroll
    for (int i = 0; i < 4; ++i) {
        const int k = (tid >> 6) + 4 * i;   // 0..15
        b_gp[i] = Wp + (size_t)k * H + nBase + b_n4 * 4;
        b_w [i] = k * BPADW + b_n4 * 4;
    }

    unsigned* Abuf[2];
    unsigned* Bbuf[2];
    #pragma unroll
    for (int b = 0; b < 2; ++b) {
        Abuf[b] = (unsigned*)(sb + b * BUFB);
        Bbuf[b] = (unsigned*)(sb + b * BUFB + ABYTES);
    }

    // stage chunk 0
    {
        #pragma unroll
        for (int i = 0; i < 2; ++i) {
            const float4 v = *(const float4*)(a_gp[i]);
            unsigned* d = &Abuf[0][a_w[i]];
            d[0] = f2tf(v.x); d[1] = f2tf(v.y); d[2] = f2tf(v.z); d[3] = f2tf(v.w);
        }
        #pragma unroll
        for (int i = 0; i < 4; ++i) {
            const float4 v = *(const float4*)(b_gp[i]);
            unsigned* d = &Bbuf[0][b_w[i]];
            d[0] = f2tf(v.x); d[1] = f2tf(v.y); d[2] = f2tf(v.z); d[3] = f2tf(v.w);
        }
    }
    __syncthreads();

    float c[4][8][4];
    #pragma unroll
    for (int mt = 0; mt < 4; ++mt)
        #pragma unroll
        for (int nt = 0; nt < 8; ++nt)
            #pragma unroll
            for (int q = 0; q < 4; ++q) c[mt][nt][q] = 0.f;

    for (int kt = 0; kt < NCHUNK; ++kt) {
        const int buf = kt & 1;

        // prefetch next chunk (gmem -> regs) before MMAs
        float4 av[2], bv[4];
        const bool more = (kt + 1 < NCHUNK);
        if (more) {
            #pragma unroll
            for (int i = 0; i < 2; ++i) av[i] = *(const float4*)(a_gp[i] + (kt + 1) * BK);
            #pragma unroll
            for (int i = 0; i < 4; ++i) bv[i] = *(const float4*)(b_gp[i] + (size_t)(kt + 1) * BK * H);
        }

        const unsigned* A = Abuf[buf];
        const unsigned* B = Bbuf[buf];

        #pragma unroll
        for (int ks = 0; ks < 2; ++ks) {
            const int kc = ks * 8 + (lane & 3);
            unsigned a[4][4], b[8][2];
            #pragma unroll
            for (int mt = 0; mt < 4; ++mt) {
                const int r = wm * 64 + mt * 16 + (lane >> 2);
                a[mt][0] = A[a_word(r,     kc)];
                a[mt][1] = A[a_word(r + 8, kc)];
                a[mt][2] = A[a_word(r,     kc + 4)];
                a[mt][3] = A[a_word(r + 8, kc + 4)];
            }
            #pragma unroll
            for (int nt = 0; nt < 8; ++nt) {
                const int ncol = wn * 64 + nt * 8 + (lane >> 2);
                b[nt][0] = B[(kc    ) * BPADW + ncol];
                b[nt][1] = B[(kc + 4) * BPADW + ncol];
            }
            #pragma unroll
            for (int mt = 0; mt < 4; ++mt)
                #pragma unroll
                for (int nt = 0; nt < 8; ++nt)
                    asm volatile(
                        "mma.sync.aligned.m16n8k8.row.col.f32.tf32.tf32.f32 "
                        "{%0,%1,%2,%3}, {%4,%5,%6,%7}, {%8,%9}, {%0,%1,%2,%3};\n"
                        : "+f"(c[mt][nt][0]), "+f"(c[mt][nt][1]),
                          "+f"(c[mt][nt][2]), "+f"(c[mt][nt][3])
                        : "r"(a[mt][0]), "r"(a[mt][1]), "r"(a[mt][2]), "r"(a[mt][3]),
                          "r"(b[nt][0]), "r"(b[nt][1]));
        }

        if (more) {
            const int nb = buf ^ 1;
            #pragma unroll
            for (int i = 0; i < 2; ++i) {
                unsigned* d = &Abuf[nb][a_w[i]];
                d[0] = f2tf(av[i].x); d[1] = f2tf(av[i].y);
                d[2] = f2tf(av[i].z); d[3] = f2tf(av[i].w);
            }
            #pragma unroll
            for (int i = 0; i < 4; ++i) {
                unsigned* d = &Bbuf[nb][b_w[i]];
                d[0] = f2tf(bv[i].x); d[1] = f2tf(bv[i].y);
                d[2] = f2tf(bv[i].z); d[3] = f2tf(bv[i].w);
            }
        }
        __syncthreads();
    }

    // ---- epilogue: scale by coef, store rows to scratch ----
    #pragma unroll
    for (int mt = 0; mt < 4; ++mt) {
        #pragma unroll
        for (int half = 0; half < 2; ++half) {
            const int r  = wm * 64 + mt * 16 + (lane >> 2) + half * 8;
            const int gm = mBase + r;
            if (gm < cnt) {
                const int   dest = d_perm_dest[e * T + gm];
                const float coef = d_perm_coef[e * T + gm];
                float* orow = d_scratch + (size_t)dest * H + nBase;
                #pragma unroll
                for (int nt = 0; nt < 8; ++nt) {
                    const int col = wn * 64 + nt * 8 + (lane & 3) * 2;
                    float2 v;
                    v.x = c[mt][nt][half * 2 + 0] * coef;
                    v.y = c[mt][nt][half * 2 + 1] * coef;
                    *(float2*)(orow + col) = v;
                }
            }
        }
    }
}

// ============================================================
// Reduce: out[t] = sum_k scratch[t*6+k] + bias[t]   (DRAM-roofline bound)
__global__ void __launch_bounds__(256) reduce_kernel(float* __restrict__ out)
{
    const int gid = blockIdx.x * blockDim.x + threadIdx.x;
    const int t   = gid >> 8;
    const float4* s = (const float4*)d_scratch;
    const size_t base = (size_t)t * TOPK * (H / 4) + (gid & 255);

    float4 a = s[base];
    #pragma unroll
    for (int k = 1; k < TOPK; ++k) {
        const float4 b = s[base + (size_t)k * (H / 4)];
        a.x += b.x; a.y += b.y; a.z += b.z; a.w += b.w;
    }
    const float bi = d_bias[t];
    a.x += bi; a.y += bi; a.z += bi; a.w += bi;
    ((float4*)out)[gid] = a;
}

// ============================================================
extern "C" void kernel_launch(void* const* d_in, const int* in_sizes, int n_in,
                              void* d_out, int out_size)
{
    const float* tokens = (const float*)d_in[0];   // [4,2048,1024]
    const float* rw     = (const float*)d_in[1];   // [16,1024]
    const float* rb     = (const float*)d_in[2];   // [16]
    const float* ew     = (const float*)d_in[3];   // [16,1024,1024]
    float* out = (float*)d_out;

    cudaFuncSetAttribute(moe_gemm_kernel,
                         cudaFuncAttributeMaxDynamicSharedMemorySize, DSMEM);

    zero_counts_kernel<<<1, 32>>>();
    router_kernel<<<T / 128, 256>>>(tokens, rw, rb);
    dim3 g(H / BN, 64, E);
    moe_gemm_kernel<<<g, 256, DSMEM>>>(tokens, ew);
    reduce_kernel<<<(T * H / 4) / 256, 256>>>(out);
}

// round 4
// speedup vs baseline: 1.4621x; 1.4621x over previous
#include <cuda_runtime.h>
#include <cuda_fp16.h>
#include <cstdint>
#include <math.h>

#define H      1024
#define E      16
#define T      8192
#define TOPK   6
#define EPSV   1e-10f

// ---- GEMM tiling: block 128M x 256N, BK=16, 512 thr, warptile 32x64 ----
#define BM 128
#define BN 256
#define BK 16
#define NCHUNK (H/BK)           // 64
#define ASTRIDE 48              // bytes per A row (16 halves = 32B, padded to 48)
#define ABYTES (128*ASTRIDE)    // 6144
#define BBYTES (16*512)         // 8192 (16 k-rows x 256 halves = 512B/row)
#define BUFB   (ABYTES+BBYTES)  // 14336
#define DSMEM  (2*BUFB + 1024)

// ---- scratch (device globals) ----
__device__ int   d_counts[E];
__device__ int   d_perm_token[E*T];
__device__ int   d_perm_dest [E*T];
__device__ float d_perm_coef [E*T];
__device__ float d_bias[T];
__device__ float d_scratch[(size_t)T*TOPK*H];   // 192 MB

// ============================================================
__device__ __forceinline__ uint32_t smem_u32(const void* p) {
    uint32_t a;
    asm("{ .reg .u64 t; cvta.to.shared.u64 t, %1; cvt.u32.u64 %0, t; }"
        : "=r"(a) : "l"(p));
    return a;
}
__device__ __forceinline__ uint32_t pk(float a, float b) {
    __half2 h = __floats2half2_rn(a, b);     // a -> low half
    return *(uint32_t*)&h;
}
__device__ __forceinline__ void ldsm4(uint32_t addr, uint32_t* r) {
    asm volatile("ldmatrix.sync.aligned.m8n8.x4.shared.b16 {%0,%1,%2,%3}, [%4];"
        : "=r"(r[0]), "=r"(r[1]), "=r"(r[2]), "=r"(r[3]) : "r"(addr));
}
__device__ __forceinline__ void ldsm4t(uint32_t addr, uint32_t* r) {
    asm volatile("ldmatrix.sync.aligned.m8n8.x4.trans.shared.b16 {%0,%1,%2,%3}, [%4];"
        : "=r"(r[0]), "=r"(r[1]), "=r"(r[2]), "=r"(r[3]) : "r"(addr));
}
__device__ __forceinline__ void mma16816(float* c, const uint32_t* a,
                                         uint32_t b0, uint32_t b1) {
    asm volatile(
        "mma.sync.aligned.m16n8k16.row.col.f32.f16.f16.f32 "
        "{%0,%1,%2,%3}, {%4,%5,%6,%7}, {%8,%9}, {%0,%1,%2,%3};\n"
        : "+f"(c[0]), "+f"(c[1]), "+f"(c[2]), "+f"(c[3])
        : "r"(a[0]), "r"(a[1]), "r"(a[2]), "r"(a[3]), "r"(b0), "r"(b1));
}

// ============================================================
__global__ void zero_counts_kernel() {
    if (threadIdx.x < E) d_counts[threadIdx.x] = 0;
}

// ============================================================
// Router: warp per token (validated in R1)
__global__ void __launch_bounds__(256) router_kernel(
    const float* __restrict__ tokens,
    const float* __restrict__ rw,
    const float* __restrict__ rb)
{
    const int warp = threadIdx.x >> 5;
    const int lane = threadIdx.x & 31;

    for (int it = 0; it < 16; ++it) {
        const int t = blockIdx.x * 128 + warp * 16 + it;

        float xr[32];
        const float* xp = tokens + (size_t)t * H;
        #pragma unroll
        for (int j = 0; j < 32; ++j) xr[j] = xp[j * 32 + lane];

        float myLogit = -INFINITY;
        #pragma unroll
        for (int e = 0; e < E; ++e) {
            const float* wp = rw + e * H;
            float s = 0.f;
            #pragma unroll
            for (int j = 0; j < 32; ++j) s += xr[j] * wp[j * 32 + lane];
            #pragma unroll
            for (int o = 16; o; o >>= 1) s += __shfl_xor_sync(0xffffffffu, s, o);
            if (lane == e) myLogit = s + rb[e];
        }

        float m = myLogit;
        #pragma unroll
        for (int o = 16; o; o >>= 1) m = fmaxf(m, __shfl_xor_sync(0xffffffffu, m, o));
        float p = (lane < E) ? expf(myLogit - m) : 0.f;
        float Z = p;
        #pragma unroll
        for (int o = 16; o; o >>= 1) Z += __shfl_xor_sync(0xffffffffu, Z, o);

        float pv[E];
        #pragma unroll
        for (int e = 0; e < E; ++e) pv[e] = __shfl_sync(0xffffffffu, p, e);

        if (lane == 0) {
            int   ids[TOPK];
            float ps [TOPK];
            float s = 0.f;
            #pragma unroll
            for (int k = 0; k < TOPK; ++k) {
                int best = 0; float bv = pv[0];
                #pragma unroll
                for (int e = 1; e < E; ++e)
                    if (pv[e] > bv) { bv = pv[e]; best = e; }
                ids[k] = best; ps[k] = bv; pv[best] = -1.f; s += bv;
            }
            #pragma unroll
            for (int k = 0; k < TOPK; ++k) {
                const float coef = ps[k] / s;
                const int e = ids[k];
                const int pos = atomicAdd(&d_counts[e], 1);
                d_perm_token[e * T + pos] = t;
                d_perm_dest [e * T + pos] = t * TOPK + k;
                d_perm_coef [e * T + pos] = coef;
            }
            const float sn = s / Z;
            d_bias[t] = EPSV * sn / (sn + EPSV);
        }
    }
}

// ============================================================
// Grouped GEMM, fp16 mma.sync m16n8k16, fp32 accum, ldmatrix fragments.
// Grid (H/BN=4, T/BM=64, E). Warps 0-7 stage A; warps 8-15 stage B.
__global__ void __launch_bounds__(512, 1) moe_gemm_kernel(
    const float* __restrict__ x,
    const float* __restrict__ ew)
{
    const int e     = blockIdx.z;
    const int cnt   = d_counts[e];
    const int mBase = blockIdx.y * BM;
    if (mBase >= cnt) return;
    const int nBase = blockIdx.x * BN;

    const float* Wp   = ew + (size_t)e * H * H;     // [K=H, N=H] row-major
    const int*   ptok = d_perm_token + e * T;

    extern __shared__ char dsm[];
    char* sb = dsm + ((1024 - (((uintptr_t)dsm) & 1023)) & 1023);
    const uint32_t sbase = smem_u32(sb);

    const int tid  = threadIdx.x;
    const int lane = tid & 31;
    const int wid  = tid >> 5;
    const int wm   = wid >> 2;      // 0..3 -> rows wm*32
    const int wn   = wid & 3;       // 0..3 -> cols wn*64

    // ---- staging maps ----
    const bool isA = (tid < 256);
    const float* g0;            // A: row ptr at k-seg; B: chunk (k0, ch)
    const float* g1;            // B only: chunk (k0+8, ch)
    uint32_t sts0 = 0, sts1 = 0;
    if (isA) {
        const int ar = tid & 127;
        const int ah = tid >> 7;                // 0/1: which 8-float half of k16
        const int gm = mBase + ar;
        const int tok = ptok[(gm < cnt) ? gm : (cnt - 1)];
        g0 = x + (size_t)tok * H + ah * 8;
        g1 = g0;                                // unused
        sts0 = ar * ASTRIDE + ah * 16;
    } else {
        const int idx = tid - 256;
        const int ch  = idx & 31;               // n chunk (8 floats)
        const int k0  = idx >> 5;               // 0..7
        g0 = Wp + (size_t)k0 * H + nBase + ch * 8;
        g1 = g0 + (size_t)8 * H;
        sts0 = ABYTES + k0 * 512 + ((ch ^ (k0 & 7)) << 4);
        sts1 = sts0 + 8 * 512;
    }

    // ---- fragment addresses (loop-invariant; add buf*BUFB) ----
    uint32_t aoff[2];
    #pragma unroll
    for (int mt = 0; mt < 2; ++mt)
        aoff[mt] = sbase + (wm * 32 + mt * 16 + (lane & 15)) * ASTRIDE
                 + (lane >> 4) * 16;
    uint32_t boff[4];
    {
        const int k = lane & 15;
        #pragma unroll
        for (int p = 0; p < 4; ++p) {
            const int ch = wn * 8 + p * 2 + (lane >> 4);
            boff[p] = sbase + ABYTES + k * 512 + ((ch ^ (k & 7)) << 4);
        }
    }

    // ---- stage chunk 0 ----
    {
        if (isA) {
            const float4 v0 = *(const float4*)(g0);
            const float4 v1 = *(const float4*)(g0 + 4);
            uint4 u; u.x = pk(v0.x, v0.y); u.y = pk(v0.z, v0.w);
                     u.z = pk(v1.x, v1.y); u.w = pk(v1.z, v1.w);
            *(uint4*)(sb + sts0) = u;
        } else {
            const float4 v0 = *(const float4*)(g0);
            const float4 v1 = *(const float4*)(g0 + 4);
            uint4 u; u.x = pk(v0.x, v0.y); u.y = pk(v0.z, v0.w);
                     u.z = pk(v1.x, v1.y); u.w = pk(v1.z, v1.w);
            *(uint4*)(sb + sts0) = u;
            const float4 w0 = *(const float4*)(g1);
            const float4 w1 = *(const float4*)(g1 + 4);
            uint4 q; q.x = pk(w0.x, w0.y); q.y = pk(w0.z, w0.w);
                     q.z = pk(w1.x, w1.y); q.w = pk(w1.z, w1.w);
            *(uint4*)(sb + sts1) = q;
        }
    }
    __syncthreads();

    float c[2][8][4];
    #pragma unroll
    for (int mt = 0; mt < 2; ++mt)
        #pragma unroll
        for (int nt = 0; nt < 8; ++nt)
            #pragma unroll
            for (int q = 0; q < 4; ++q) c[mt][nt][q] = 0.f;

    for (int kt = 0; kt < NCHUNK; ++kt) {
        const int buf = kt & 1;
        const uint32_t bofs = buf * BUFB;
        const bool more = (kt + 1 < NCHUNK);

        // prefetch next chunk to registers
        float4 p0, p1, p2, p3;
        if (more) {
            if (isA) {
                const float* g = g0 + (kt + 1) * BK;
                p0 = *(const float4*)(g);
                p1 = *(const float4*)(g + 4);
            } else {
                const size_t adv = (size_t)(kt + 1) * BK * H;
                p0 = *(const float4*)(g0 + adv);
                p1 = *(const float4*)(g0 + adv + 4);
                p2 = *(const float4*)(g1 + adv);
                p3 = *(const float4*)(g1 + adv + 4);
            }
        }

        // fragments + MMAs
        uint32_t afr[2][4];
        #pragma unroll
        for (int mt = 0; mt < 2; ++mt) ldsm4(aoff[mt] + bofs, afr[mt]);
        #pragma unroll
        for (int p = 0; p < 4; ++p) {
            uint32_t bfr[4];
            ldsm4t(boff[p] + bofs, bfr);
            #pragma unroll
            for (int mt = 0; mt < 2; ++mt) {
                mma16816(c[mt][p * 2 + 0], afr[mt], bfr[0], bfr[1]);
                mma16816(c[mt][p * 2 + 1], afr[mt], bfr[2], bfr[3]);
            }
        }

        // store prefetched chunk
        if (more) {
            char* nb = sb + (buf ^ 1) * BUFB;
            if (isA) {
                uint4 u; u.x = pk(p0.x, p0.y); u.y = pk(p0.z, p0.w);
                         u.z = pk(p1.x, p1.y); u.w = pk(p1.z, p1.w);
                *(uint4*)(nb + sts0) = u;
            } else {
                uint4 u; u.x = pk(p0.x, p0.y); u.y = pk(p0.z, p0.w);
                         u.z = pk(p1.x, p1.y); u.w = pk(p1.z, p1.w);
                *(uint4*)(nb + sts0) = u;
                uint4 q; q.x = pk(p2.x, p2.y); q.y = pk(p2.z, p2.w);
                         q.z = pk(p3.x, p3.y); q.w = pk(p3.z, p3.w);
                *(uint4*)(nb + sts1) = q;
            }
        }
        __syncthreads();
    }

    // ---- epilogue: scale by coef, store rows to scratch ----
    #pragma unroll
    for (int mt = 0; mt < 2; ++mt) {
        #pragma unroll
        for (int half = 0; half < 2; ++half) {
            const int r  = wm * 32 + mt * 16 + (lane >> 2) + half * 8;
            const int gm = mBase + r;
            if (gm < cnt) {
                const int   dest = d_perm_dest[e * T + gm];
                const float coef = d_perm_coef[e * T + gm];
                float* orow = d_scratch + (size_t)dest * H + nBase;
                #pragma unroll
                for (int nt = 0; nt < 8; ++nt) {
                    const int col = wn * 64 + nt * 8 + (lane & 3) * 2;
                    float2 v;
                    v.x = c[mt][nt][half * 2 + 0] * coef;
                    v.y = c[mt][nt][half * 2 + 1] * coef;
                    *(float2*)(orow + col) = v;
                }
            }
        }
    }
}

// ============================================================
// Reduce: out[t] = sum_k scratch[t*6+k] + bias[t]   (DRAM-bound, 35us)
__global__ void __launch_bounds__(256) reduce_kernel(float* __restrict__ out)
{
    const int gid = blockIdx.x * blockDim.x + threadIdx.x;
    const int t   = gid >> 8;
    const float4* s = (const float4*)d_scratch;
    const size_t base = (size_t)t * TOPK * (H / 4) + (gid & 255);

    float4 a = s[base];
    #pragma unroll
    for (int k = 1; k < TOPK; ++k) {
        const float4 b = s[base + (size_t)k * (H / 4)];
        a.x += b.x; a.y += b.y; a.z += b.z; a.w += b.w;
    }
    const float bi = d_bias[t];
    a.x += bi; a.y += bi; a.z += bi; a.w += bi;
    ((float4*)out)[gid] = a;
}

// ============================================================
extern "C" void kernel_launch(void* const* d_in, const int* in_sizes, int n_in,
                              void* d_out, int out_size)
{
    const float* tokens = (const float*)d_in[0];
    const float* rw     = (const float*)d_in[1];
    const float* rb     = (const float*)d_in[2];
    const float* ew     = (const float*)d_in[3];
    float* out = (float*)d_out;

    cudaFuncSetAttribute(moe_gemm_kernel,
                         cudaFuncAttributeMaxDynamicSharedMemorySize, DSMEM);

    zero_counts_kernel<<<1, 32>>>();
    router_kernel<<<T / 128, 256>>>(tokens, rw, rb);
    dim3 g(H / BN, T / BM, E);
    moe_gemm_kernel<<<g, 512, DSMEM>>>(tokens, ew);
    reduce_kernel<<<(T * H / 4) / 256, 256>>>(out);
}

// round 5
// speedup vs baseline: 2.3059x; 1.5771x over previous
#include <cuda_runtime.h>
#include <cuda_fp16.h>
#include <cstdint>
#include <math.h>

#define H      1024
#define E      16
#define T      8192
#define TOPK   6
#define EPSV   1e-10f

// ---- GEMM tiling: block 128M x 128N, BK=16, 256 thr, 8 warps (4x2), 2 CTA/SM
#define BM 128
#define BN 128
#define BK 16
#define NCHUNK (H/BK)           // 64
#define STAGES 4
#define ASTG (128*48)           // 6144: A rows at 48B stride (16 halves used)
#define BSTG (16*256)           // 4096: B 16 k-rows x 128 halves (256B/row)
#define STGB (ASTG+BSTG)        // 10240
#define DSMEM (STAGES*STGB + 1024)

// ---- device globals (no allocation allowed) ----
__device__ int    d_counts[E];
__device__ int    d_perm_token[E*T];
__device__ int    d_perm_dest [E*T];
__device__ float  d_perm_coef [E*T];
__device__ float  d_bias[T];
__device__ __half d_x16[(size_t)T*H];          // 16 MB
__device__ __half d_w16[(size_t)E*H*H];        // 32 MB
__device__ __half d_scratch16[(size_t)T*TOPK*H]; // 96 MB

// ============================================================
__device__ __forceinline__ uint32_t smem_u32(const void* p) {
    uint32_t a;
    asm("{ .reg .u64 t; cvta.to.shared.u64 t, %1; cvt.u32.u64 %0, t; }"
        : "=r"(a) : "l"(p));
    return a;
}
__device__ __forceinline__ uint32_t pk(float a, float b) {
    __half2 h = __floats2half2_rn(a, b);
    return *(uint32_t*)&h;
}
__device__ __forceinline__ void ldsm4(uint32_t addr, uint32_t* r) {
    asm volatile("ldmatrix.sync.aligned.m8n8.x4.shared.b16 {%0,%1,%2,%3}, [%4];"
        : "=r"(r[0]), "=r"(r[1]), "=r"(r[2]), "=r"(r[3]) : "r"(addr));
}
__device__ __forceinline__ void ldsm4t(uint32_t addr, uint32_t* r) {
    asm volatile("ldmatrix.sync.aligned.m8n8.x4.trans.shared.b16 {%0,%1,%2,%3}, [%4];"
        : "=r"(r[0]), "=r"(r[1]), "=r"(r[2]), "=r"(r[3]) : "r"(addr));
}
__device__ __forceinline__ void mma16816(float* c, const uint32_t* a,
                                         uint32_t b0, uint32_t b1) {
    asm volatile(
        "mma.sync.aligned.m16n8k16.row.col.f32.f16.f16.f32 "
        "{%0,%1,%2,%3}, {%4,%5,%6,%7}, {%8,%9}, {%0,%1,%2,%3};\n"
        : "+f"(c[0]), "+f"(c[1]), "+f"(c[2]), "+f"(c[3])
        : "r"(a[0]), "r"(a[1]), "r"(a[2]), "r"(a[3]), "r"(b0), "r"(b1));
}
__device__ __forceinline__ void cpa16(uint32_t dst, const void* src) {
    asm volatile("cp.async.cg.shared.global [%0], [%1], 16;"
                 :: "r"(dst), "l"(src) : "memory");
}
#define CP_COMMIT() asm volatile("cp.async.commit_group;" ::: "memory")
#define CP_WAIT2()  asm volatile("cp.async.wait_group 2;"  ::: "memory")

// ============================================================
__global__ void zero_counts_kernel() {
    if (threadIdx.x < E) d_counts[threadIdx.x] = 0;
}

// Convert fp32 -> fp16 (8 elems/thread)
__global__ void __launch_bounds__(256) cvt_kernel(const float* __restrict__ src,
                                                  __half* __restrict__ dst) {
    const size_t i = ((size_t)blockIdx.x * 256 + threadIdx.x) * 8;
    const float4 a = *(const float4*)(src + i);
    const float4 b = *(const float4*)(src + i + 4);
    uint4 u;
    u.x = pk(a.x, a.y); u.y = pk(a.z, a.w);
    u.z = pk(b.x, b.y); u.w = pk(b.z, b.w);
    *(uint4*)(dst + i) = u;
}

// ============================================================
// Router: warp per token (validated R1)
__global__ void __launch_bounds__(256) router_kernel(
    const float* __restrict__ tokens,
    const float* __restrict__ rw,
    const float* __restrict__ rb)
{
    const int warp = threadIdx.x >> 5;
    const int lane = threadIdx.x & 31;

    for (int it = 0; it < 16; ++it) {
        const int t = blockIdx.x * 128 + warp * 16 + it;

        float xr[32];
        const float* xp = tokens + (size_t)t * H;
        #pragma unroll
        for (int j = 0; j < 32; ++j) xr[j] = xp[j * 32 + lane];

        float myLogit = -INFINITY;
        #pragma unroll
        for (int e = 0; e < E; ++e) {
            const float* wp = rw + e * H;
            float s = 0.f;
            #pragma unroll
            for (int j = 0; j < 32; ++j) s += xr[j] * wp[j * 32 + lane];
            #pragma unroll
            for (int o = 16; o; o >>= 1) s += __shfl_xor_sync(0xffffffffu, s, o);
            if (lane == e) myLogit = s + rb[e];
        }

        float m = myLogit;
        #pragma unroll
        for (int o = 16; o; o >>= 1) m = fmaxf(m, __shfl_xor_sync(0xffffffffu, m, o));
        float p = (lane < E) ? expf(myLogit - m) : 0.f;
        float Z = p;
        #pragma unroll
        for (int o = 16; o; o >>= 1) Z += __shfl_xor_sync(0xffffffffu, Z, o);

        float pv[E];
        #pragma unroll
        for (int e = 0; e < E; ++e) pv[e] = __shfl_sync(0xffffffffu, p, e);

        if (lane == 0) {
            int   ids[TOPK];
            float ps [TOPK];
            float s = 0.f;
            #pragma unroll
            for (int k = 0; k < TOPK; ++k) {
                int best = 0; float bv = pv[0];
                #pragma unroll
                for (int e = 1; e < E; ++e)
                    if (pv[e] > bv) { bv = pv[e]; best = e; }
                ids[k] = best; ps[k] = bv; pv[best] = -1.f; s += bv;
            }
            #pragma unroll
            for (int k = 0; k < TOPK; ++k) {
                const float coef = ps[k] / s;
                const int e = ids[k];
                const int pos = atomicAdd(&d_counts[e], 1);
                d_perm_token[e * T + pos] = t;
                d_perm_dest [e * T + pos] = t * TOPK + k;
                d_perm_coef [e * T + pos] = coef;
            }
            const float sn = s / Z;
            d_bias[t] = EPSV * sn / (sn + EPSV);
        }
    }
}

// ============================================================
// Grouped GEMM: fp16 mma m16n8k16 / fp32 accum, cp.async 4-stage pipeline.
// Grid (H/BN=8, T/BM=64, E). 256 threads, 2 CTA/SM.
__global__ void __launch_bounds__(256, 2) moe_gemm_kernel()
{
    const int e     = blockIdx.z;
    const int cnt   = d_counts[e];
    const int mBase = blockIdx.y * BM;
    if (mBase >= cnt) return;
    const int nBase = blockIdx.x * BN;

    const __half* Wp   = d_w16 + (size_t)e * H * H;
    const int*    ptok = d_perm_token + e * T;

    extern __shared__ char dsm[];
    char* sb = dsm + ((256 - (((uintptr_t)dsm) & 255)) & 255);
    const uint32_t sbase = smem_u32(sb);

    const int tid  = threadIdx.x;
    const int lane = tid & 31;
    const int wid  = tid >> 5;
    const int wm   = wid >> 1;      // 0..3 -> rows wm*32
    const int wn   = wid & 1;       // 0..1 -> cols wn*64

    // ---- cp.async source/dest maps (1 A chunk + 1 B chunk per thread) ----
    const int a_row = tid >> 1;                 // 0..127
    const int a_h   = tid & 1;                  // 16B half of k16
    const int a_gm  = mBase + a_row;
    const int a_tok = ptok[(a_gm < cnt) ? a_gm : (cnt - 1)];
    const __half* a_src = d_x16 + (size_t)a_tok * H + a_h * 8;
    const uint32_t a_dst = a_row * 48 + a_h * 16;

    const int b_k  = tid >> 4;                  // 0..15
    const int b_ch = tid & 15;                  // 0..15 (16B chunks along N)
    const __half* b_src = Wp + (size_t)b_k * H + nBase + b_ch * 8;
    const uint32_t b_dst = ASTG + b_k * 256 + (((b_ch ^ (b_k & 7))) << 4);

    // ---- fragment addresses (add stage*STGB) ----
    uint32_t aoff[2];
    #pragma unroll
    for (int mt = 0; mt < 2; ++mt)
        aoff[mt] = sbase + (wm * 32 + mt * 16 + (lane & 15)) * 48
                 + (lane >> 4) * 16;
    uint32_t boff[4];
    {
        const int k = lane & 15;
        #pragma unroll
        for (int p = 0; p < 4; ++p) {
            const int ch = wn * 8 + p * 2 + (lane >> 4);
            boff[p] = sbase + ASTG + k * 256 + ((ch ^ (k & 7)) << 4);
        }
    }

    // ---- pipeline prologue: stages 0..2 = chunks 0..2 ----
    #pragma unroll
    for (int s = 0; s < STAGES - 1; ++s) {
        const uint32_t so = sbase + s * STGB;
        cpa16(so + a_dst, a_src + s * BK);
        cpa16(so + b_dst, b_src + (size_t)s * BK * H);
        CP_COMMIT();
    }

    float c[2][8][4];
    #pragma unroll
    for (int mt = 0; mt < 2; ++mt)
        #pragma unroll
        for (int nt = 0; nt < 8; ++nt)
            #pragma unroll
            for (int q = 0; q < 4; ++q) c[mt][nt][q] = 0.f;

    for (int kt = 0; kt < NCHUNK; ++kt) {
        CP_WAIT2();
        __syncthreads();

        const uint32_t bofs = (kt & (STAGES - 1)) * STGB;

        uint32_t afr[2][4];
        #pragma unroll
        for (int mt = 0; mt < 2; ++mt) ldsm4(aoff[mt] + bofs, afr[mt]);
        #pragma unroll
        for (int p = 0; p < 4; ++p) {
            uint32_t bfr[4];
            ldsm4t(boff[p] + bofs, bfr);
            #pragma unroll
            for (int mt = 0; mt < 2; ++mt) {
                mma16816(c[mt][p * 2 + 0], afr[mt], bfr[0], bfr[1]);
                mma16816(c[mt][p * 2 + 1], afr[mt], bfr[2], bfr[3]);
            }
        }

        const int nc = kt + STAGES - 1;
        if (nc < NCHUNK) {
            const uint32_t so = sbase + (nc & (STAGES - 1)) * STGB;
            cpa16(so + a_dst, a_src + nc * BK);
            cpa16(so + b_dst, b_src + (size_t)nc * BK * H);
        }
        CP_COMMIT();   // empty commits in tail keep group accounting exact
    }

    // ---- epilogue: scale by coef, store fp16 rows to scratch ----
    #pragma unroll
    for (int mt = 0; mt < 2; ++mt) {
        #pragma unroll
        for (int half = 0; half < 2; ++half) {
            const int r  = wm * 32 + mt * 16 + (lane >> 2) + half * 8;
            const int gm = mBase + r;
            if (gm < cnt) {
                const int   dest = d_perm_dest[e * T + gm];
                const float coef = d_perm_coef[e * T + gm];
                __half* orow = d_scratch16 + (size_t)dest * H + nBase;
                #pragma unroll
                for (int nt = 0; nt < 8; ++nt) {
                    const int col = wn * 64 + nt * 8 + (lane & 3) * 2;
                    *(uint32_t*)(orow + col) =
                        pk(c[mt][nt][half * 2 + 0] * coef,
                           c[mt][nt][half * 2 + 1] * coef);
                }
            }
        }
    }
}

// ============================================================
// Reduce: out[t, 8 cols] = sum_k scratch16[(t*6+k)] + bias[t]
__global__ void __launch_bounds__(256) reduce_kernel(float* __restrict__ out)
{
    const int gid = blockIdx.x * blockDim.x + threadIdx.x;
    const int t   = gid >> 7;                 // H/8 = 128 per token
    const int c8  = gid & 127;
    const __half* base = d_scratch16 + (size_t)t * TOPK * H + c8 * 8;

    float acc[8];
    #pragma unroll
    for (int j = 0; j < 8; ++j) acc[j] = 0.f;
    #pragma unroll
    for (int k = 0; k < TOPK; ++k) {
        const uint4 v = *(const uint4*)(base + (size_t)k * H);
        const uint32_t w[4] = {v.x, v.y, v.z, v.w};
        #pragma unroll
        for (int j = 0; j < 4; ++j) {
            const float2 f = __half22float2(*(const __half2*)&w[j]);
            acc[j * 2 + 0] += f.x;
            acc[j * 2 + 1] += f.y;
        }
    }
    const float bi = d_bias[t];
    float* op = out + (size_t)t * H + c8 * 8;
    float4 o0, o1;
    o0.x = acc[0] + bi; o0.y = acc[1] + bi; o0.z = acc[2] + bi; o0.w = acc[3] + bi;
    o1.x = acc[4] + bi; o1.y = acc[5] + bi; o1.z = acc[6] + bi; o1.w = acc[7] + bi;
    *(float4*)(op)     = o0;
    *(float4*)(op + 4) = o1;
}

// ============================================================
extern "C" void kernel_launch(void* const* d_in, const int* in_sizes, int n_in,
                              void* d_out, int out_size)
{
    const float* tokens = (const float*)d_in[0];
    const float* rw     = (const float*)d_in[1];
    const float* rb     = (const float*)d_in[2];
    const float* ew     = (const float*)d_in[3];
    float* out = (float*)d_out;

    cudaFuncSetAttribute(moe_gemm_kernel,
                         cudaFuncAttributeMaxDynamicSharedMemorySize, DSMEM);

    __half* x16p; cudaGetSymbolAddress((void**)&x16p, d_x16);
    __half* w16p; cudaGetSymbolAddress((void**)&w16p, d_w16);

    zero_counts_kernel<<<1, 32>>>();
    cvt_kernel<<<(int)(((size_t)T * H) / (256 * 8)), 256>>>(tokens, x16p);
    cvt_kernel<<<(int)(((size_t)E * H * H) / (256 * 8)), 256>>>(ew, w16p);
    router_kernel<<<T / 128, 256>>>(tokens, rw, rb);
    dim3 g(H / BN, T / BM, E);
    moe_gemm_kernel<<<g, 256, DSMEM>>>();
    reduce_kernel<<<(T * H / 8) / 256, 256>>>(out);
}

// round 6
// speedup vs baseline: 3.5453x; 1.5374x over previous
#include <cuda_runtime.h>
#include <cuda_fp16.h>
#include <cstdint>
#include <math.h>

#define H      1024
#define E      16
#define T      8192
#define TOPK   6
#define EPSV   1e-10f

// ---- GEMM tiling: block 128M x 128N, BK=16, 256 thr, 8 warps (4x2), 2 CTA/SM
#define BM 128
#define BN 128
#define BK 16
#define NCHUNK (H/BK)           // 64
#define STAGES 4
#define ASTG (128*48)           // 6144: A rows at 48B stride (16 halves used)
#define BSTG (16*256)           // 4096: B 16 k-rows x 128 halves (256B/row)
#define STGB (ASTG+BSTG)        // 10240
#define DSMEM (STAGES*STGB + 1024)

// ---- device globals (no allocation allowed) ----
__device__ int    d_counts[E];
__device__ int    d_perm_token[E*T];
__device__ int    d_perm_dest [E*T];
__device__ float  d_perm_coef [E*T];
__device__ float  d_bias[T];
__device__ __half d_x16[(size_t)T*H];          // 16 MB
__device__ __half d_w16[(size_t)E*H*H];        // 32 MB
__device__ __half d_scratch16[(size_t)T*TOPK*H]; // 96 MB

// ============================================================
__device__ __forceinline__ uint32_t smem_u32(const void* p) {
    uint32_t a;
    asm("{ .reg .u64 t; cvta.to.shared.u64 t, %1; cvt.u32.u64 %0, t; }"
        : "=r"(a) : "l"(p));
    return a;
}
__device__ __forceinline__ uint32_t pk(float a, float b) {
    __half2 h = __floats2half2_rn(a, b);
    return *(uint32_t*)&h;
}
__device__ __forceinline__ void ldsm4(uint32_t addr, uint32_t* r) {
    asm volatile("ldmatrix.sync.aligned.m8n8.x4.shared.b16 {%0,%1,%2,%3}, [%4];"
        : "=r"(r[0]), "=r"(r[1]), "=r"(r[2]), "=r"(r[3]) : "r"(addr));
}
__device__ __forceinline__ void ldsm4t(uint32_t addr, uint32_t* r) {
    asm volatile("ldmatrix.sync.aligned.m8n8.x4.trans.shared.b16 {%0,%1,%2,%3}, [%4];"
        : "=r"(r[0]), "=r"(r[1]), "=r"(r[2]), "=r"(r[3]) : "r"(addr));
}
__device__ __forceinline__ void mma16816(float* c, const uint32_t* a,
                                         uint32_t b0, uint32_t b1) {
    asm volatile(
        "mma.sync.aligned.m16n8k16.row.col.f32.f16.f16.f32 "
        "{%0,%1,%2,%3}, {%4,%5,%6,%7}, {%8,%9}, {%0,%1,%2,%3};\n"
        : "+f"(c[0]), "+f"(c[1]), "+f"(c[2]), "+f"(c[3])
        : "r"(a[0]), "r"(a[1]), "r"(a[2]), "r"(a[3]), "r"(b0), "r"(b1));
}
__device__ __forceinline__ void cpa16(uint32_t dst, const void* src) {
    asm volatile("cp.async.cg.shared.global [%0], [%1], 16;"
                 :: "r"(dst), "l"(src) : "memory");
}
#define CP_COMMIT() asm volatile("cp.async.commit_group;" ::: "memory")
#define CP_WAIT2()  asm volatile("cp.async.wait_group 2;"  ::: "memory")

// ============================================================
__global__ void zero_counts_kernel() {
    if (threadIdx.x < E) d_counts[threadIdx.x] = 0;
}

// Convert fp32 -> fp16 (8 elems/thread)
__global__ void __launch_bounds__(256) cvt_kernel(const float* __restrict__ src,
                                                  __half* __restrict__ dst) {
    const size_t i = ((size_t)blockIdx.x * 256 + threadIdx.x) * 8;
    const float4 a = *(const float4*)(src + i);
    const float4 b = *(const float4*)(src + i + 4);
    uint4 u;
    u.x = pk(a.x, a.y); u.y = pk(a.z, a.w);
    u.z = pk(b.x, b.y); u.w = pk(b.z, b.w);
    *(uint4*)(dst + i) = u;
}

// ============================================================
// Router: ONE token per warp, 1024 blocks (was 64 -> latency-bound, 263us).
// float4 loads; rw (64KB) is L1-resident.
__global__ void __launch_bounds__(256) router_kernel(
    const float* __restrict__ tokens,
    const float* __restrict__ rw,
    const float* __restrict__ rb)
{
    const int warp = threadIdx.x >> 5;
    const int lane = threadIdx.x & 31;
    const int t = blockIdx.x * 8 + warp;

    // lane loads 8 float4s: elements [j*128 + lane*4 .. +3], j = 0..7
    float4 xr[8];
    const float4* xp = (const float4*)(tokens + (size_t)t * H);
    #pragma unroll
    for (int j = 0; j < 8; ++j) xr[j] = xp[j * 32 + lane];

    float myLogit = 0.f;
    #pragma unroll
    for (int e = 0; e < E; ++e) {
        const float4* wp = (const float4*)(rw + e * H);
        float s = 0.f;
        #pragma unroll
        for (int j = 0; j < 8; ++j) {
            const float4 w = wp[j * 32 + lane];
            s += xr[j].x * w.x + xr[j].y * w.y + xr[j].z * w.z + xr[j].w * w.w;
        }
        #pragma unroll
        for (int o = 16; o; o >>= 1) s += __shfl_xor_sync(0xffffffffu, s, o);
        if (lane == e) myLogit = s + rb[e];
    }

    // softmax over lanes 0..15
    float m = (lane < E) ? myLogit : -INFINITY;
    #pragma unroll
    for (int o = 16; o; o >>= 1) m = fmaxf(m, __shfl_xor_sync(0xffffffffu, m, o));
    float p = (lane < E) ? expf(myLogit - m) : 0.f;
    float Z = p;
    #pragma unroll
    for (int o = 16; o; o >>= 1) Z += __shfl_xor_sync(0xffffffffu, Z, o);

    float pv[E];
    #pragma unroll
    for (int e = 0; e < E; ++e) pv[e] = __shfl_sync(0xffffffffu, p, e);

    if (lane == 0) {
        int   ids[TOPK];
        float ps [TOPK];
        float s = 0.f;
        #pragma unroll
        for (int k = 0; k < TOPK; ++k) {
            int best = 0; float bv = pv[0];
            #pragma unroll
            for (int e = 1; e < E; ++e)
                if (pv[e] > bv) { bv = pv[e]; best = e; }
            ids[k] = best; ps[k] = bv; pv[best] = -1.f; s += bv;
        }
        #pragma unroll
        for (int k = 0; k < TOPK; ++k) {
            const float coef = ps[k] / s;
            const int e = ids[k];
            const int pos = atomicAdd(&d_counts[e], 1);
            d_perm_token[e * T + pos] = t;
            d_perm_dest [e * T + pos] = t * TOPK + k;
            d_perm_coef [e * T + pos] = coef;
        }
        const float sn = s / Z;
        d_bias[t] = EPSV * sn / (sn + EPSV);
    }
}

// ============================================================
// Grouped GEMM: fp16 mma m16n8k16 / fp32 accum, cp.async 4-stage pipeline.
// Grid (H/BN=8, T/BM=64, E). 256 threads, 2 CTA/SM.  (At legacy fp16 ceiling.)
__global__ void __launch_bounds__(256, 2) moe_gemm_kernel()
{
    const int e     = blockIdx.z;
    const int cnt   = d_counts[e];
    const int mBase = blockIdx.y * BM;
    if (mBase >= cnt) return;
    const int nBase = blockIdx.x * BN;

    const __half* Wp   = d_w16 + (size_t)e * H * H;
    const int*    ptok = d_perm_token + e * T;

    extern __shared__ char dsm[];
    char* sb = dsm + ((256 - (((uintptr_t)dsm) & 255)) & 255);
    const uint32_t sbase = smem_u32(sb);

    const int tid  = threadIdx.x;
    const int lane = tid & 31;
    const int wid  = tid >> 5;
    const int wm   = wid >> 1;      // 0..3 -> rows wm*32
    const int wn   = wid & 1;       // 0..1 -> cols wn*64

    // ---- cp.async source/dest maps (1 A chunk + 1 B chunk per thread) ----
    const int a_row = tid >> 1;                 // 0..127
    const int a_h   = tid & 1;                  // 16B half of k16
    const int a_gm  = mBase + a_row;
    const int a_tok = ptok[(a_gm < cnt) ? a_gm : (cnt - 1)];
    const __half* a_src = d_x16 + (size_t)a_tok * H + a_h * 8;
    const uint32_t a_dst = a_row * 48 + a_h * 16;

    const int b_k  = tid >> 4;                  // 0..15
    const int b_ch = tid & 15;                  // 0..15 (16B chunks along N)
    const __half* b_src = Wp + (size_t)b_k * H + nBase + b_ch * 8;
    const uint32_t b_dst = ASTG + b_k * 256 + (((b_ch ^ (b_k & 7))) << 4);

    // ---- fragment addresses (add stage*STGB) ----
    uint32_t aoff[2];
    #pragma unroll
    for (int mt = 0; mt < 2; ++mt)
        aoff[mt] = sbase + (wm * 32 + mt * 16 + (lane & 15)) * 48
                 + (lane >> 4) * 16;
    uint32_t boff[4];
    {
        const int k = lane & 15;
        #pragma unroll
        for (int p = 0; p < 4; ++p) {
            const int ch = wn * 8 + p * 2 + (lane >> 4);
            boff[p] = sbase + ASTG + k * 256 + ((ch ^ (k & 7)) << 4);
        }
    }

    // ---- pipeline prologue: stages 0..2 = chunks 0..2 ----
    #pragma unroll
    for (int s = 0; s < STAGES - 1; ++s) {
        const uint32_t so = sbase + s * STGB;
        cpa16(so + a_dst, a_src + s * BK);
        cpa16(so + b_dst, b_src + (size_t)s * BK * H);
        CP_COMMIT();
    }

    float c[2][8][4];
    #pragma unroll
    for (int mt = 0; mt < 2; ++mt)
        #pragma unroll
        for (int nt = 0; nt < 8; ++nt)
            #pragma unroll
            for (int q = 0; q < 4; ++q) c[mt][nt][q] = 0.f;

    for (int kt = 0; kt < NCHUNK; ++kt) {
        CP_WAIT2();
        __syncthreads();

        const uint32_t bofs = (kt & (STAGES - 1)) * STGB;

        uint32_t afr[2][4];
        #pragma unroll
        for (int mt = 0; mt < 2; ++mt) ldsm4(aoff[mt] + bofs, afr[mt]);
        #pragma unroll
        for (int p = 0; p < 4; ++p) {
            uint32_t bfr[4];
            ldsm4t(boff[p] + bofs, bfr);
            #pragma unroll
            for (int mt = 0; mt < 2; ++mt) {
                mma16816(c[mt][p * 2 + 0], afr[mt], bfr[0], bfr[1]);
                mma16816(c[mt][p * 2 + 1], afr[mt], bfr[2], bfr[3]);
            }
        }

        const int nc = kt + STAGES - 1;
        if (nc < NCHUNK) {
            const uint32_t so = sbase + (nc & (STAGES - 1)) * STGB;
            cpa16(so + a_dst, a_src + nc * BK);
            cpa16(so + b_dst, b_src + (size_t)nc * BK * H);
        }
        CP_COMMIT();   // empty commits in tail keep group accounting exact
    }

    // ---- epilogue: scale by coef, store fp16 rows to scratch ----
    #pragma unroll
    for (int mt = 0; mt < 2; ++mt) {
        #pragma unroll
        for (int half = 0; half < 2; ++half) {
            const int r  = wm * 32 + mt * 16 + (lane >> 2) + half * 8;
            const int gm = mBase + r;
            if (gm < cnt) {
                const int   dest = d_perm_dest[e * T + gm];
                const float coef = d_perm_coef[e * T + gm];
                __half* orow = d_scratch16 + (size_t)dest * H + nBase;
                #pragma unroll
                for (int nt = 0; nt < 8; ++nt) {
                    const int col = wn * 64 + nt * 8 + (lane & 3) * 2;
                    *(uint32_t*)(orow + col) =
                        pk(c[mt][nt][half * 2 + 0] * coef,
                           c[mt][nt][half * 2 + 1] * coef);
                }
            }
        }
    }
}

// ============================================================
// Reduce: out[t, 8 cols] = sum_k scratch16[(t*6+k)] + bias[t]
__global__ void __launch_bounds__(256) reduce_kernel(float* __restrict__ out)
{
    const int gid = blockIdx.x * blockDim.x + threadIdx.x;
    const int t   = gid >> 7;                 // H/8 = 128 per token
    const int c8  = gid & 127;
    const __half* base = d_scratch16 + (size_t)t * TOPK * H + c8 * 8;

    float acc[8];
    #pragma unroll
    for (int j = 0; j < 8; ++j) acc[j] = 0.f;
    #pragma unroll
    for (int k = 0; k < TOPK; ++k) {
        const uint4 v = *(const uint4*)(base + (size_t)k * H);
        const uint32_t w[4] = {v.x, v.y, v.z, v.w};
        #pragma unroll
        for (int j = 0; j < 4; ++j) {
            const float2 f = __half22float2(*(const __half2*)&w[j]);
            acc[j * 2 + 0] += f.x;
            acc[j * 2 + 1] += f.y;
        }
    }
    const float bi = d_bias[t];
    float* op = out + (size_t)t * H + c8 * 8;
    float4 o0, o1;
    o0.x = acc[0] + bi; o0.y = acc[1] + bi; o0.z = acc[2] + bi; o0.w = acc[3] + bi;
    o1.x = acc[4] + bi; o1.y = acc[5] + bi; o1.z = acc[6] + bi; o1.w = acc[7] + bi;
    *(float4*)(op)     = o0;
    *(float4*)(op + 4) = o1;
}

// ============================================================
extern "C" void kernel_launch(void* const* d_in, const int* in_sizes, int n_in,
                              void* d_out, int out_size)
{
    const float* tokens = (const float*)d_in[0];
    const float* rw     = (const float*)d_in[1];
    const float* rb     = (const float*)d_in[2];
    const float* ew     = (const float*)d_in[3];
    float* out = (float*)d_out;

    cudaFuncSetAttribute(moe_gemm_kernel,
                         cudaFuncAttributeMaxDynamicSharedMemorySize, DSMEM);

    __half* x16p; cudaGetSymbolAddress((void**)&x16p, d_x16);
    __half* w16p; cudaGetSymbolAddress((void**)&w16p, d_w16);

    zero_counts_kernel<<<1, 32>>>();
    cvt_kernel<<<(int)(((size_t)T * H) / (256 * 8)), 256>>>(tokens, x16p);
    cvt_kernel<<<(int)(((size_t)E * H * H) / (256 * 8)), 256>>>(ew, w16p);
    router_kernel<<<T / 8, 256>>>(tokens, rw, rb);
    dim3 g(H / BN, T / BM, E);
    moe_gemm_kernel<<<g, 256, DSMEM>>>();
    reduce_kernel<<<(T * H / 8) / 256, 256>>>(out);
}

// round 7
// speedup vs baseline: 3.7935x; 1.0700x over previous
#include <cuda_runtime.h>
#include <cuda_fp16.h>
#include <cstdint>
#include <math.h>

#define H      1024
#define E      16
#define T      8192
#define TOPK   6
#define EPSV   1e-10f

// ---- GEMM tiling: 128M x 128N, BK=32, 256 thr, 8 warps (4x2), 2 CTA/SM ----
#define BM 128
#define BN 128
#define BK 32
#define NCHUNK (H/BK)           // 32
#define STAGES 3
#define ASTG (128*64)           // 8192: A 128 rows x 64B (32 halves), slot-swizzled
#define BSTG (32*256)           // 8192: B 32 k-rows x 256B (128 halves)
#define STGB (ASTG+BSTG)        // 16384
#define DSMEM (STAGES*STGB + 1024)

// ---- device globals (no allocation allowed) ----
__device__ int    d_counts[E];
__device__ int    d_perm_token[E*T];
__device__ int    d_perm_dest [E*T];
__device__ float  d_perm_coef [E*T];
__device__ float  d_bias[T];
__device__ __half d_x16[(size_t)T*H];            // 16 MB (written by router)
__device__ __half d_w16[(size_t)E*H*H];          // 32 MB
__device__ __half d_scratch16[(size_t)T*TOPK*H]; // 96 MB

// ============================================================
__device__ __forceinline__ uint32_t smem_u32(const void* p) {
    uint32_t a;
    asm("{ .reg .u64 t; cvta.to.shared.u64 t, %1; cvt.u32.u64 %0, t; }"
        : "=r"(a) : "l"(p));
    return a;
}
__device__ __forceinline__ uint32_t pk(float a, float b) {
    __half2 h = __floats2half2_rn(a, b);
    return *(uint32_t*)&h;
}
__device__ __forceinline__ void ldsm4(uint32_t addr, uint32_t* r) {
    asm volatile("ldmatrix.sync.aligned.m8n8.x4.shared.b16 {%0,%1,%2,%3}, [%4];"
        : "=r"(r[0]), "=r"(r[1]), "=r"(r[2]), "=r"(r[3]) : "r"(addr));
}
__device__ __forceinline__ void ldsm4t(uint32_t addr, uint32_t* r) {
    asm volatile("ldmatrix.sync.aligned.m8n8.x4.trans.shared.b16 {%0,%1,%2,%3}, [%4];"
        : "=r"(r[0]), "=r"(r[1]), "=r"(r[2]), "=r"(r[3]) : "r"(addr));
}
__device__ __forceinline__ void mma16816(float* c, const uint32_t* a,
                                         uint32_t b0, uint32_t b1) {
    asm volatile(
        "mma.sync.aligned.m16n8k16.row.col.f32.f16.f16.f32 "
        "{%0,%1,%2,%3}, {%4,%5,%6,%7}, {%8,%9}, {%0,%1,%2,%3};\n"
        : "+f"(c[0]), "+f"(c[1]), "+f"(c[2]), "+f"(c[3])
        : "r"(a[0]), "r"(a[1]), "r"(a[2]), "r"(a[3]), "r"(b0), "r"(b1));
}
__device__ __forceinline__ void cpa16(uint32_t dst, const void* src) {
    asm volatile("cp.async.cg.shared.global [%0], [%1], 16;"
                 :: "r"(dst), "l"(src) : "memory");
}
#define CP_COMMIT() asm volatile("cp.async.commit_group;" ::: "memory")
#define CP_WAIT1()  asm volatile("cp.async.wait_group 1;"  ::: "memory")

// ============================================================
__global__ void zero_counts_kernel() {
    if (threadIdx.x < E) d_counts[threadIdx.x] = 0;
}

// Convert fp32 -> fp16 (8 elems/thread) — used for W only
__global__ void __launch_bounds__(256) cvt_kernel(const float* __restrict__ src,
                                                  __half* __restrict__ dst) {
    const size_t i = ((size_t)blockIdx.x * 256 + threadIdx.x) * 8;
    const float4 a = *(const float4*)(src + i);
    const float4 b = *(const float4*)(src + i + 4);
    uint4 u;
    u.x = pk(a.x, a.y); u.y = pk(a.z, a.w);
    u.z = pk(b.x, b.y); u.w = pk(b.z, b.w);
    *(uint4*)(dst + i) = u;
}

// ============================================================
// Router: warp per token; streams x once, accumulates all 16 experts.
// Also writes the fp16 copy of x (fuses old cvt_x kernel).
__global__ void __launch_bounds__(256) router_kernel(
    const float* __restrict__ tokens,
    const float* __restrict__ rw,
    const float* __restrict__ rb)
{
    const int warp = threadIdx.x >> 5;
    const int lane = threadIdx.x & 31;
    const int t = blockIdx.x * 8 + warp;

    float s[E];
    #pragma unroll
    for (int e = 0; e < E; ++e) s[e] = 0.f;

    const float4* xp = (const float4*)(tokens + (size_t)t * H);
    #pragma unroll
    for (int j2 = 0; j2 < 4; ++j2) {
        // x elements [j2*256 + lane*8 .. +7]
        const float4 xa = xp[j2 * 64 + lane * 2 + 0];
        const float4 xb = xp[j2 * 64 + lane * 2 + 1];
        // fused fp16 conversion (coalesced uint4 stores)
        uint4 u;
        u.x = pk(xa.x, xa.y); u.y = pk(xa.z, xa.w);
        u.z = pk(xb.x, xb.y); u.w = pk(xb.z, xb.w);
        *(uint4*)(d_x16 + (size_t)t * H + j2 * 256 + lane * 8) = u;

        #pragma unroll
        for (int e = 0; e < E; ++e) {
            const float4* wp = (const float4*)(rw + e * H) + j2 * 64 + lane * 2;
            const float4 wa = wp[0];
            const float4 wb = wp[1];
            s[e] += xa.x * wa.x + xa.y * wa.y + xa.z * wa.z + xa.w * wa.w
                  + xb.x * wb.x + xb.y * wb.y + xb.z * wb.z + xb.w * wb.w;
        }
    }

    // butterfly-reduce each expert sum across the warp
    #pragma unroll
    for (int e = 0; e < E; ++e) {
        #pragma unroll
        for (int o = 16; o; o >>= 1) s[e] += __shfl_xor_sync(0xffffffffu, s[e], o);
    }

    if (lane == 0) {
        float pv[E];
        float m = -INFINITY;
        #pragma unroll
        for (int e = 0; e < E; ++e) {
            pv[e] = s[e] + rb[e];
            m = fmaxf(m, pv[e]);
        }
        float Z = 0.f;
        #pragma unroll
        for (int e = 0; e < E; ++e) { pv[e] = expf(pv[e] - m); Z += pv[e]; }

        int   ids[TOPK];
        float ps [TOPK];
        float ssum = 0.f;
        #pragma unroll
        for (int k = 0; k < TOPK; ++k) {
            int best = 0; float bv = pv[0];
            #pragma unroll
            for (int e = 1; e < E; ++e)
                if (pv[e] > bv) { bv = pv[e]; best = e; }
            ids[k] = best; ps[k] = bv; pv[best] = -1.f; ssum += bv;
        }
        #pragma unroll
        for (int k = 0; k < TOPK; ++k) {
            const float coef = ps[k] / ssum;
            const int e = ids[k];
            const int pos = atomicAdd(&d_counts[e], 1);
            d_perm_token[e * T + pos] = t;
            d_perm_dest [e * T + pos] = t * TOPK + k;
            d_perm_coef [e * T + pos] = coef;
        }
        const float sn = ssum / Z;
        d_bias[t] = EPSV * sn / (sn + EPSV);
    }
}

// ============================================================
// Grouped GEMM: fp16 mma m16n8k16 / fp32 accum, cp.async 3-stage, BK=32.
// Grid (H/BN=8, T/BM=64, E). 256 threads, 2 CTA/SM.
__global__ void __launch_bounds__(256, 2) moe_gemm_kernel()
{
    const int e     = blockIdx.z;
    const int cnt   = d_counts[e];
    const int mBase = blockIdx.y * BM;
    if (mBase >= cnt) return;
    const int nBase = blockIdx.x * BN;

    const __half* Wp   = d_w16 + (size_t)e * H * H;
    const int*    ptok = d_perm_token + e * T;

    extern __shared__ char dsm[];
    char* sb = dsm + ((256 - (((uintptr_t)dsm) & 255)) & 255);
    const uint32_t sbase = smem_u32(sb);

    const int tid  = threadIdx.x;
    const int lane = tid & 31;
    const int wid  = tid >> 5;
    const int wm   = wid >> 1;      // 0..3 -> rows wm*32
    const int wn   = wid & 1;       // 0..1 -> cols wn*64

    // ---- cp.async maps: 2 A-chunks + 2 B-chunks of 16B per thread/chunk ----
    const __half* a_src[2];
    uint32_t a_dst[2];
    #pragma unroll
    for (int j = 0; j < 2; ++j) {
        const int i   = tid + 256 * j;
        const int row = i >> 2;                  // 0..127
        const int c   = i & 3;                   // 16B slot within 64B row
        const int gm  = mBase + row;
        const int tok = ptok[(gm < cnt) ? gm : (cnt - 1)];
        a_src[j] = d_x16 + (size_t)tok * H + c * 8;
        a_dst[j] = row * 64 + ((c ^ ((row >> 1) & 3)) << 4);
    }
    const __half* b_src[2];
    uint32_t b_dst[2];
    #pragma unroll
    for (int j = 0; j < 2; ++j) {
        const int i  = tid + 256 * j;
        const int k  = i >> 4;                   // 0..31
        const int ch = i & 15;                   // 16B chunk along N
        b_src[j] = Wp + (size_t)k * H + nBase + ch * 8;
        b_dst[j] = ASTG + k * 256 + ((ch ^ (k & 7)) << 4);
    }

    // ---- fragment addresses (loop-invariant; add stage offset) ----
    uint32_t aoff[2][2];     // [mt][g]
    #pragma unroll
    for (int mt = 0; mt < 2; ++mt) {
        const int row = wm * 32 + mt * 16 + (lane & 15);
        #pragma unroll
        for (int g = 0; g < 2; ++g) {
            const int ci = g * 2 + (lane >> 4);
            aoff[mt][g] = sbase + row * 64 + ((ci ^ ((row >> 1) & 3)) << 4);
        }
    }
    uint32_t boff[2][4];     // [g][p]
    #pragma unroll
    for (int g = 0; g < 2; ++g) {
        const int k = g * 16 + (lane & 15);
        #pragma unroll
        for (int p = 0; p < 4; ++p) {
            const int ch = wn * 8 + p * 2 + (lane >> 4);
            boff[g][p] = sbase + ASTG + k * 256 + ((ch ^ (k & 7)) << 4);
        }
    }

    // ---- prologue: stage chunks 0,1 ----
    #pragma unroll
    for (int s = 0; s < STAGES - 1; ++s) {
        const uint32_t so = s * STGB;
        #pragma unroll
        for (int j = 0; j < 2; ++j) {
            cpa16(sbase + so + a_dst[j], a_src[j] + s * BK);
            cpa16(sbase + so + b_dst[j], b_src[j] + (size_t)s * BK * H);
        }
        CP_COMMIT();
    }

    float c[2][8][4];
    #pragma unroll
    for (int mt = 0; mt < 2; ++mt)
        #pragma unroll
        for (int nt = 0; nt < 8; ++nt)
            #pragma unroll
            for (int q = 0; q < 4; ++q) c[mt][nt][q] = 0.f;

    int stage = 0, pstage = STAGES - 1;   // pstage: stage for chunk kt+2
    for (int kt = 0; kt < NCHUNK; ++kt) {
        CP_WAIT1();
        __syncthreads();

        const uint32_t bofs = stage * STGB;

        #pragma unroll
        for (int g = 0; g < 2; ++g) {
            uint32_t afr[2][4];
            #pragma unroll
            for (int mt = 0; mt < 2; ++mt) ldsm4(aoff[mt][g] + bofs, afr[mt]);
            #pragma unroll
            for (int p = 0; p < 4; ++p) {
                uint32_t bfr[4];
                ldsm4t(boff[g][p] + bofs, bfr);
                #pragma unroll
                for (int mt = 0; mt < 2; ++mt) {
                    mma16816(c[mt][p * 2 + 0], afr[mt], bfr[0], bfr[1]);
                    mma16816(c[mt][p * 2 + 1], afr[mt], bfr[2], bfr[3]);
                }
            }
        }

        const int nc = kt + STAGES - 1;
        if (nc < NCHUNK) {
            const uint32_t so = pstage * STGB;
            #pragma unroll
            for (int j = 0; j < 2; ++j) {
                cpa16(sbase + so + a_dst[j], a_src[j] + nc * BK);
                cpa16(sbase + so + b_dst[j], b_src[j] + (size_t)nc * BK * H);
            }
        }
        CP_COMMIT();   // empty commits in tail keep group accounting exact

        if (++stage == STAGES)  stage = 0;
        if (++pstage == STAGES) pstage = 0;
    }

    // ---- epilogue: scale by coef, store fp16 rows to scratch ----
    #pragma unroll
    for (int mt = 0; mt < 2; ++mt) {
        #pragma unroll
        for (int half = 0; half < 2; ++half) {
            const int r  = wm * 32 + mt * 16 + (lane >> 2) + half * 8;
            const int gm = mBase + r;
            if (gm < cnt) {
                const int   dest = d_perm_dest[e * T + gm];
                const float coef = d_perm_coef[e * T + gm];
                __half* orow = d_scratch16 + (size_t)dest * H + nBase;
                #pragma unroll
                for (int nt = 0; nt < 8; ++nt) {
                    const int col = wn * 64 + nt * 8 + (lane & 3) * 2;
                    *(uint32_t*)(orow + col) =
                        pk(c[mt][nt][half * 2 + 0] * coef,
                           c[mt][nt][half * 2 + 1] * coef);
                }
            }
        }
    }
}

// ============================================================
// Reduce: out[t, 8 cols] = sum_k scratch16[(t*6+k)] + bias[t]
__global__ void __launch_bounds__(256) reduce_kernel(float* __restrict__ out)
{
    const int gid = blockIdx.x * blockDim.x + threadIdx.x;
    const int t   = gid >> 7;                 // H/8 = 128 per token
    const int c8  = gid & 127;
    const __half* base = d_scratch16 + (size_t)t * TOPK * H + c8 * 8;

    float acc[8];
    #pragma unroll
    for (int j = 0; j < 8; ++j) acc[j] = 0.f;
    #pragma unroll
    for (int k = 0; k < TOPK; ++k) {
        const uint4 v = *(const uint4*)(base + (size_t)k * H);
        const uint32_t w[4] = {v.x, v.y, v.z, v.w};
        #pragma unroll
        for (int j = 0; j < 4; ++j) {
            const float2 f = __half22float2(*(const __half2*)&w[j]);
            acc[j * 2 + 0] += f.x;
            acc[j * 2 + 1] += f.y;
        }
    }
    const float bi = d_bias[t];
    float* op = out + (size_t)t * H + c8 * 8;
    float4 o0, o1;
    o0.x = acc[0] + bi; o0.y = acc[1] + bi; o0.z = acc[2] + bi; o0.w = acc[3] + bi;
    o1.x = acc[4] + bi; o1.y = acc[5] + bi; o1.z = acc[6] + bi; o1.w = acc[7] + bi;
    *(float4*)(op)     = o0;
    *(float4*)(op + 4) = o1;
}

// ============================================================
extern "C" void kernel_launch(void* const* d_in, const int* in_sizes, int n_in,
                              void* d_out, int out_size)
{
    const float* tokens = (const float*)d_in[0];
    const float* rw     = (const float*)d_in[1];
    const float* rb     = (const float*)d_in[2];
    const float* ew     = (const float*)d_in[3];
    float* out = (float*)d_out;

    cudaFuncSetAttribute(moe_gemm_kernel,
                         cudaFuncAttributeMaxDynamicSharedMemorySize, DSMEM);

    __half* w16p; cudaGetSymbolAddress((void**)&w16p, d_w16);

    zero_counts_kernel<<<1, 32>>>();
    cvt_kernel<<<(int)(((size_t)E * H * H) / (256 * 8)), 256>>>(ew, w16p);
    router_kernel<<<T / 8, 256>>>(tokens, rw, rb);
    dim3 g(H / BN, T / BM, E);
    moe_gemm_kernel<<<g, 256, DSMEM>>>();
    reduce_kernel<<<(T * H / 8) / 256, 256>>>(out);
}

// round 8
// speedup vs baseline: 4.1283x; 1.0883x over previous
#include <cuda_runtime.h>
#include <cuda_fp16.h>
#include <cstdint>
#include <math.h>

#define H      1024
#define E      16
#define T      8192
#define TOPK   6
#define EPSV   1e-10f

// ---- GEMM tiling: 128M x 128N, BK=64, 256 thr, 8 warps (4x2), 2 CTA/SM ----
#define BM 128
#define BN 128
#define BK 64
#define NCHUNK (H/BK)           // 16
#define STAGES 3
#define ASTG (128*128)          // 16384: A 128 rows x 128B (64 halves), SW128
#define BSTG (64*256)           // 16384: B 64 k-rows x 256B (128 halves)
#define STGB (ASTG+BSTG)        // 32768
#define DSMEM (STAGES*STGB + 256)

// ---- device globals (no allocation allowed) ----
__device__ int    d_counts[E];
__device__ int    d_perm_token[E*T];
__device__ int    d_perm_dest [E*T];
__device__ float  d_perm_coef [E*T];
__device__ float  d_bias[T];
__device__ __half d_x16[(size_t)T*H];            // 16 MB (written by router)
__device__ __half d_w16[(size_t)E*H*H];          // 32 MB
__device__ __half d_scratch16[(size_t)T*TOPK*H]; // 96 MB

// ============================================================
__device__ __forceinline__ uint32_t smem_u32(const void* p) {
    uint32_t a;
    asm("{ .reg .u64 t; cvta.to.shared.u64 t, %1; cvt.u32.u64 %0, t; }"
        : "=r"(a) : "l"(p));
    return a;
}
__device__ __forceinline__ uint32_t pk(float a, float b) {
    __half2 h = __floats2half2_rn(a, b);
    return *(uint32_t*)&h;
}
__device__ __forceinline__ void ldsm4(uint32_t addr, uint32_t* r) {
    asm volatile("ldmatrix.sync.aligned.m8n8.x4.shared.b16 {%0,%1,%2,%3}, [%4];"
        : "=r"(r[0]), "=r"(r[1]), "=r"(r[2]), "=r"(r[3]) : "r"(addr));
}
__device__ __forceinline__ void ldsm4t(uint32_t addr, uint32_t* r) {
    asm volatile("ldmatrix.sync.aligned.m8n8.x4.trans.shared.b16 {%0,%1,%2,%3}, [%4];"
        : "=r"(r[0]), "=r"(r[1]), "=r"(r[2]), "=r"(r[3]) : "r"(addr));
}
__device__ __forceinline__ void mma16816(float* c, const uint32_t* a,
                                         uint32_t b0, uint32_t b1) {
    asm volatile(
        "mma.sync.aligned.m16n8k16.row.col.f32.f16.f16.f32 "
        "{%0,%1,%2,%3}, {%4,%5,%6,%7}, {%8,%9}, {%0,%1,%2,%3};\n"
        : "+f"(c[0]), "+f"(c[1]), "+f"(c[2]), "+f"(c[3])
        : "r"(a[0]), "r"(a[1]), "r"(a[2]), "r"(a[3]), "r"(b0), "r"(b1));
}
__device__ __forceinline__ void cpa16(uint32_t dst, const void* src) {
    asm volatile("cp.async.cg.shared.global [%0], [%1], 16;"
                 :: "r"(dst), "l"(src) : "memory");
}
#define CP_COMMIT() asm volatile("cp.async.commit_group;" ::: "memory")
#define CP_WAIT1()  asm volatile("cp.async.wait_group 1;"  ::: "memory")

// ============================================================
// Convert W fp32 -> fp16 (8 elems/thread); block 0 also zeroes counts.
__global__ void __launch_bounds__(256) cvt_kernel(const float* __restrict__ src,
                                                  __half* __restrict__ dst) {
    if (blockIdx.x == 0 && threadIdx.x < E) d_counts[threadIdx.x] = 0;
    const size_t i = ((size_t)blockIdx.x * 256 + threadIdx.x) * 8;
    const float4 a = *(const float4*)(src + i);
    const float4 b = *(const float4*)(src + i + 4);
    uint4 u;
    u.x = pk(a.x, a.y); u.y = pk(a.z, a.w);
    u.z = pk(b.x, b.y); u.w = pk(b.z, b.w);
    *(uint4*)(dst + i) = u;
}

// ============================================================
// Router: warp per token; streams x once, accumulates all 16 experts,
// writes fp16 x copy (fused conversion).
__global__ void __launch_bounds__(256) router_kernel(
    const float* __restrict__ tokens,
    const float* __restrict__ rw,
    const float* __restrict__ rb)
{
    const int warp = threadIdx.x >> 5;
    const int lane = threadIdx.x & 31;
    const int t = blockIdx.x * 8 + warp;

    float s[E];
    #pragma unroll
    for (int e = 0; e < E; ++e) s[e] = 0.f;

    const float4* xp = (const float4*)(tokens + (size_t)t * H);
    #pragma unroll
    for (int j2 = 0; j2 < 4; ++j2) {
        const float4 xa = xp[j2 * 64 + lane * 2 + 0];
        const float4 xb = xp[j2 * 64 + lane * 2 + 1];
        uint4 u;
        u.x = pk(xa.x, xa.y); u.y = pk(xa.z, xa.w);
        u.z = pk(xb.x, xb.y); u.w = pk(xb.z, xb.w);
        *(uint4*)(d_x16 + (size_t)t * H + j2 * 256 + lane * 8) = u;

        #pragma unroll
        for (int e = 0; e < E; ++e) {
            const float4* wp = (const float4*)(rw + e * H) + j2 * 64 + lane * 2;
            const float4 wa = wp[0];
            const float4 wb = wp[1];
            s[e] += xa.x * wa.x + xa.y * wa.y + xa.z * wa.z + xa.w * wa.w
                  + xb.x * wb.x + xb.y * wb.y + xb.z * wb.z + xb.w * wb.w;
        }
    }

    #pragma unroll
    for (int e = 0; e < E; ++e) {
        #pragma unroll
        for (int o = 16; o; o >>= 1) s[e] += __shfl_xor_sync(0xffffffffu, s[e], o);
    }

    if (lane == 0) {
        float pv[E];
        float m = -INFINITY;
        #pragma unroll
        for (int e = 0; e < E; ++e) {
            pv[e] = s[e] + rb[e];
            m = fmaxf(m, pv[e]);
        }
        float Z = 0.f;
        #pragma unroll
        for (int e = 0; e < E; ++e) { pv[e] = expf(pv[e] - m); Z += pv[e]; }

        int   ids[TOPK];
        float ps [TOPK];
        float ssum = 0.f;
        #pragma unroll
        for (int k = 0; k < TOPK; ++k) {
            int best = 0; float bv = pv[0];
            #pragma unroll
            for (int e = 1; e < E; ++e)
                if (pv[e] > bv) { bv = pv[e]; best = e; }
            ids[k] = best; ps[k] = bv; pv[best] = -1.f; ssum += bv;
        }
        #pragma unroll
        for (int k = 0; k < TOPK; ++k) {
            const float coef = ps[k] / ssum;
            const int e = ids[k];
            const int pos = atomicAdd(&d_counts[e], 1);
            d_perm_token[e * T + pos] = t;
            d_perm_dest [e * T + pos] = t * TOPK + k;
            d_perm_coef [e * T + pos] = coef;
        }
        const float sn = ssum / Z;
        d_bias[t] = EPSV * sn / (sn + EPSV);
    }
}

// ============================================================
// Grouped GEMM: fp16 mma m16n8k16 / fp32 accum, cp.async 3-stage, BK=64.
// Grid (H/BN=8, T/BM=64, E). 256 threads, 2 CTA/SM.
__global__ void __launch_bounds__(256, 2) moe_gemm_kernel()
{
    const int e     = blockIdx.z;
    const int cnt   = d_counts[e];
    const int mBase = blockIdx.y * BM;
    if (mBase >= cnt) return;
    const int nBase = blockIdx.x * BN;

    const __half* Wp   = d_w16 + (size_t)e * H * H;
    const int*    ptok = d_perm_token + e * T;

    extern __shared__ char dsm[];
    char* sb = dsm + ((256 - (((uintptr_t)dsm) & 255)) & 255);
    const uint32_t sbase = smem_u32(sb);

    const int tid  = threadIdx.x;
    const int lane = tid & 31;
    const int wid  = tid >> 5;
    const int wm   = wid >> 1;      // 0..3 -> rows wm*32
    const int wn   = wid & 1;       // 0..1 -> cols wn*64

    // ---- cp.async maps (4 A + 4 B 16B chunks per thread per k-chunk) ----
    // A: i = tid + 256j -> row = i>>3 (row&... = (tid>>3)&7 const since +32j),
    //    slot c = tid&7; dst = row*128 + ((c ^ (row&7))<<4); dst[j]=dst0+4096j
    const int a_row0 = tid >> 3;               // 0..31
    const int a_c    = tid & 7;
    const uint32_t a_dst0 = a_row0 * 128 + ((a_c ^ (a_row0 & 7)) << 4);
    const __half* a_src[4];
    #pragma unroll
    for (int j = 0; j < 4; ++j) {
        const int gm = mBase + a_row0 + 32 * j;
        const int tok = ptok[(gm < cnt) ? gm : (cnt - 1)];
        a_src[j] = d_x16 + (size_t)tok * H + a_c * 8;
    }
    // B: i = tid + 256j -> k = i>>4 (k&7 const), ch = tid&15
    const int b_k0 = tid >> 4;                 // 0..15
    const int b_ch = tid & 15;
    const uint32_t b_dst0 = ASTG + b_k0 * 256 + ((b_ch ^ (b_k0 & 7)) << 4);
    const __half* b_src0 = Wp + (size_t)b_k0 * H + nBase + b_ch * 8;

    // ---- fragment addresses ----
    // A: row = wm*32+mt*16+(lane&15); slot(g) = (g*2 + h) ^ (row&7)
    //    = (g<<1) ^ (h ^ (row&7))  [no carry: h=bit0, g*2=bits1+]
    const int h = lane >> 4;
    uint32_t arowbase[2];
    uint32_t as0[2];
    #pragma unroll
    for (int mt = 0; mt < 2; ++mt) {
        const int row = wm * 32 + mt * 16 + (lane & 15);
        arowbase[mt] = sbase + row * 128;
        as0[mt] = (uint32_t)(h ^ (row & 7));
    }
    // B: k = g*16 + (lane&15) -> k&7 const; boff(g,p) = boff0[p] + g*4096
    uint32_t boff0[4];
    {
        const int k = lane & 15;
        #pragma unroll
        for (int p = 0; p < 4; ++p) {
            const int ch = wn * 8 + p * 2 + h;
            boff0[p] = sbase + ASTG + k * 256 + ((ch ^ (k & 7)) << 4);
        }
    }

    // ---- prologue: stage chunks 0,1 ----
    #pragma unroll
    for (int s = 0; s < STAGES - 1; ++s) {
        const uint32_t so = sbase + s * STGB;
        #pragma unroll
        for (int j = 0; j < 4; ++j) {
            cpa16(so + a_dst0 + j * 4096, a_src[j] + s * BK);
            cpa16(so + b_dst0 + j * 4096, b_src0 + (size_t)(16 * j + s * BK) * H);
        }
        CP_COMMIT();
    }

    float c[2][8][4];
    #pragma unroll
    for (int mt = 0; mt < 2; ++mt)
        #pragma unroll
        for (int nt = 0; nt < 8; ++nt)
            #pragma unroll
            for (int q = 0; q < 4; ++q) c[mt][nt][q] = 0.f;

    int stage = 0, pstage = STAGES - 1;
    for (int kt = 0; kt < NCHUNK; ++kt) {
        CP_WAIT1();
        __syncthreads();

        const uint32_t bofs = stage * STGB;

        #pragma unroll
        for (int g = 0; g < 4; ++g) {
            uint32_t afr[2][4];
            #pragma unroll
            for (int mt = 0; mt < 2; ++mt)
                ldsm4(arowbase[mt] + bofs + (((g << 1) ^ as0[mt]) << 4), afr[mt]);
            #pragma unroll
            for (int p = 0; p < 4; ++p) {
                uint32_t bfr[4];
                ldsm4t(boff0[p] + bofs + g * 4096, bfr);
                #pragma unroll
                for (int mt = 0; mt < 2; ++mt) {
                    mma16816(c[mt][p * 2 + 0], afr[mt], bfr[0], bfr[1]);
                    mma16816(c[mt][p * 2 + 1], afr[mt], bfr[2], bfr[3]);
                }
            }
        }

        const int nc = kt + STAGES - 1;
        if (nc < NCHUNK) {
            const uint32_t so = sbase + pstage * STGB;
            #pragma unroll
            for (int j = 0; j < 4; ++j) {
                cpa16(so + a_dst0 + j * 4096, a_src[j] + nc * BK);
                cpa16(so + b_dst0 + j * 4096, b_src0 + (size_t)(16 * j + nc * BK) * H);
            }
        }
        CP_COMMIT();

        if (++stage == STAGES)  stage = 0;
        if (++pstage == STAGES) pstage = 0;
    }

    // ---- epilogue: scale by coef, store fp16 rows to scratch ----
    #pragma unroll
    for (int mt = 0; mt < 2; ++mt) {
        #pragma unroll
        for (int half = 0; half < 2; ++half) {
            const int r  = wm * 32 + mt * 16 + (lane >> 2) + half * 8;
            const int gm = mBase + r;
            if (gm < cnt) {
                const int   dest = d_perm_dest[e * T + gm];
                const float coef = d_perm_coef[e * T + gm];
                __half* orow = d_scratch16 + (size_t)dest * H + nBase;
                #pragma unroll
                for (int nt = 0; nt < 8; ++nt) {
                    const int col = wn * 64 + nt * 8 + (lane & 3) * 2;
                    *(uint32_t*)(orow + col) =
                        pk(c[mt][nt][half * 2 + 0] * coef,
                           c[mt][nt][half * 2 + 1] * coef);
                }
            }
        }
    }
}

// ============================================================
// Reduce: out[t, 8 cols] = sum_k scratch16[(t*6+k)] + bias[t]
__global__ void __launch_bounds__(256) reduce_kernel(float* __restrict__ out)
{
    const int gid = blockIdx.x * blockDim.x + threadIdx.x;
    const int t   = gid >> 7;
    const int c8  = gid & 127;
    const __half* base = d_scratch16 + (size_t)t * TOPK * H + c8 * 8;

    float acc[8];
    #pragma unroll
    for (int j = 0; j < 8; ++j) acc[j] = 0.f;
    #pragma unroll
    for (int k = 0; k < TOPK; ++k) {
        const uint4 v = *(const uint4*)(base + (size_t)k * H);
        const uint32_t w[4] = {v.x, v.y, v.z, v.w};
        #pragma unroll
        for (int j = 0; j < 4; ++j) {
            const float2 f = __half22float2(*(const __half2*)&w[j]);
            acc[j * 2 + 0] += f.x;
            acc[j * 2 + 1] += f.y;
        }
    }
    const float bi = d_bias[t];
    float* op = out + (size_t)t * H + c8 * 8;
    float4 o0, o1;
    o0.x = acc[0] + bi; o0.y = acc[1] + bi; o0.z = acc[2] + bi; o0.w = acc[3] + bi;
    o1.x = acc[4] + bi; o1.y = acc[5] + bi; o1.z = acc[6] + bi; o1.w = acc[7] + bi;
    *(float4*)(op)     = o0;
    *(float4*)(op + 4) = o1;
}

// ============================================================
extern "C" void kernel_launch(void* const* d_in, const int* in_sizes, int n_in,
                              void* d_out, int out_size)
{
    const float* tokens = (const float*)d_in[0];
    const float* rw     = (const float*)d_in[1];
    const float* rb     = (const float*)d_in[2];
    const float* ew     = (const float*)d_in[3];
    float* out = (float*)d_out;

    cudaFuncSetAttribute(moe_gemm_kernel,
                         cudaFuncAttributeMaxDynamicSharedMemorySize, DSMEM);

    __half* w16p; cudaGetSymbolAddress((void**)&w16p, d_w16);

    cvt_kernel<<<(int)(((size_t)E * H * H) / (256 * 8)), 256>>>(ew, w16p);
    router_kernel<<<T / 8, 256>>>(tokens, rw, rb);
    dim3 g(H / BN, T / BM, E);
    moe_gemm_kernel<<<g, 256, DSMEM>>>();
    reduce_kernel<<<(T * H / 8) / 256, 256>>>(out);
}

// round 10
// speedup vs baseline: 4.2638x; 1.0328x over previous
#include <cuda_runtime.h>
#include <cuda_fp16.h>
#include <cstdint>
#include <math.h>

#define H      1024
#define E      16
#define T      8192
#define TOPK   6
#define EPSV   1e-10f

// ---- main GEMM tiling (UNCHANGED from R8) ----
#define BM 128
#define BN 128
#define BK 64
#define NCHUNK (H/BK)           // 16
#define STAGES 3
#define ASTG (128*128)          // 16384
#define BSTG (64*256)           // 16384
#define STGB (ASTG+BSTG)        // 32768
#define DSMEM (STAGES*STGB + 256)

// ---- logits mini-GEMM (hi/lo split) ----
#define LSTG   32768            // A stage: hi 16KB + lo 16KB
#define LBOFF  (3*LSTG)         // persistent B tables after 3 A stages
#define LDSMEM (LBOFF + 2*32768 + 256)

// ---- device globals (no allocation allowed) ----
__device__ int    d_counts[E];
__device__ int    d_perm_token[E*T];
__device__ int    d_perm_dest [E*T];
__device__ float  d_perm_coef [E*T];
__device__ float  d_bias[T];
__device__ float  d_logits[(size_t)T*E];         // 512 KB
__device__ __half d_x16[(size_t)T*H];            // 16 MB (hi)
__device__ __half d_xlo[(size_t)T*H];            // 16 MB (lo residual)
__device__ __half d_w16[(size_t)E*H*H];          // 32 MB
__device__ __half d_scratch16[(size_t)T*TOPK*H]; // 96 MB

// ============================================================
__device__ __forceinline__ uint32_t smem_u32(const void* p) {
    uint32_t a;
    asm("{ .reg .u64 t; cvta.to.shared.u64 t, %1; cvt.u32.u64 %0, t; }"
        : "=r"(a) : "l"(p));
    return a;
}
__device__ __forceinline__ uint32_t pk(float a, float b) {
    __half2 h = __floats2half2_rn(a, b);
    return *(uint32_t*)&h;
}
__device__ __forceinline__ void ldsm4(uint32_t addr, uint32_t* r) {
    asm volatile("ldmatrix.sync.aligned.m8n8.x4.shared.b16 {%0,%1,%2,%3}, [%4];"
        : "=r"(r[0]), "=r"(r[1]), "=r"(r[2]), "=r"(r[3]) : "r"(addr));
}
__device__ __forceinline__ void ldsm4t(uint32_t addr, uint32_t* r) {
    asm volatile("ldmatrix.sync.aligned.m8n8.x4.trans.shared.b16 {%0,%1,%2,%3}, [%4];"
        : "=r"(r[0]), "=r"(r[1]), "=r"(r[2]), "=r"(r[3]) : "r"(addr));
}
__device__ __forceinline__ void mma16816(float* c, const uint32_t* a,
                                         uint32_t b0, uint32_t b1) {
    asm volatile(
        "mma.sync.aligned.m16n8k16.row.col.f32.f16.f16.f32 "
        "{%0,%1,%2,%3}, {%4,%5,%6,%7}, {%8,%9}, {%0,%1,%2,%3};\n"
        : "+f"(c[0]), "+f"(c[1]), "+f"(c[2]), "+f"(c[3])
        : "r"(a[0]), "r"(a[1]), "r"(a[2]), "r"(a[3]), "r"(b0), "r"(b1));
}
__device__ __forceinline__ void cpa16(uint32_t dst, const void* src) {
    asm volatile("cp.async.cg.shared.global [%0], [%1], 16;"
                 :: "r"(dst), "l"(src) : "memory");
}
#define CP_COMMIT() asm volatile("cp.async.commit_group;" ::: "memory")
#define CP_WAIT1()  asm volatile("cp.async.wait_group 1;"  ::: "memory")

// ============================================================
// Convert W fp32 -> fp16 (8 elems/thread); block 0 also zeroes counts.
__global__ void __launch_bounds__(256) cvt_kernel(const float* __restrict__ src,
                                                  __half* __restrict__ dst) {
    if (blockIdx.x == 0 && threadIdx.x < E) d_counts[threadIdx.x] = 0;
    const size_t i = ((size_t)blockIdx.x * 256 + threadIdx.x) * 8;
    const float4 a = *(const float4*)(src + i);
    const float4 b = *(const float4*)(src + i + 4);
    uint4 u;
    u.x = pk(a.x, a.y); u.y = pk(a.z, a.w);
    u.z = pk(b.x, b.y); u.w = pk(b.z, b.w);
    *(uint4*)(dst + i) = u;
}

// Convert x fp32 -> fp16 hi + lo residual (8 elems/thread).
__global__ void __launch_bounds__(256) cvtx_kernel(const float* __restrict__ src) {
    const size_t i = ((size_t)blockIdx.x * 256 + threadIdx.x) * 8;
    float v[8];
    *(float4*)(v)     = *(const float4*)(src + i);
    *(float4*)(v + 4) = *(const float4*)(src + i + 4);
    __half hi[8];
    float  lo[8];
    #pragma unroll
    for (int j = 0; j < 8; ++j) {
        hi[j] = __float2half(v[j]);
        lo[j] = v[j] - __half2float(hi[j]);
    }
    *(uint4*)(d_x16 + i) = *(const uint4*)hi;
    uint4 ul;
    ul.x = pk(lo[0], lo[1]); ul.y = pk(lo[2], lo[3]);
    ul.z = pk(lo[4], lo[5]); ul.w = pk(lo[6], lo[7]);
    *(uint4*)(d_xlo + i) = ul;
}

// ============================================================
// Logits mini-GEMM: logits = xh@wh^T + xh@wl^T + xl@wh^T  (fp32-accurate).
// Grid = T/128 CTAs, 256 threads (8 warps x 16 rows).
__global__ void __launch_bounds__(256) logits_kernel(const float* __restrict__ rw)
{
    const int mBase = blockIdx.x * 128;

    extern __shared__ char dsm[];
    char* sb = dsm + ((256 - (((uintptr_t)dsm) & 255)) & 255);
    const uint32_t sbase = smem_u32(sb);

    const int tid  = threadIdx.x;
    const int lane = tid & 31;
    const int wid  = tid >> 5;
    const int h    = lane >> 4;

    // ---- build persistent B tables: wh, wl at [k 0..1023][e 0..15] ----
    {
        const int e = tid >> 4;
        const int kb = (tid & 15) * 4;
        #pragma unroll
        for (int c = 0; c < 16; ++c) {
            const int k = c * 64 + kb;
            const float4 v = *(const float4*)(rw + e * H + k);
            const float vv[4] = {v.x, v.y, v.z, v.w};
            #pragma unroll
            for (int j = 0; j < 4; ++j) {
                const int kk = k + j;
                const uint32_t off = kk * 32
                    + ((((e >> 3) ^ ((kk >> 2) & 1))) << 4) + (e & 7) * 2;
                const __half hh = __float2half(vv[j]);
                const __half hl = __float2half(vv[j] - __half2float(hh));
                *(__half*)(sb + LBOFF + off)         = hh;
                *(__half*)(sb + LBOFF + 32768 + off) = hl;
            }
        }
    }

    // ---- A staging maps (same math as main GEMM; hi + lo per stage) ----
    const int a_row0 = tid >> 3;               // 0..31
    const int a_c    = tid & 7;
    const uint32_t a_dst0 = a_row0 * 128 + ((a_c ^ (a_row0 & 7)) << 4);
    const size_t a_goff = (size_t)(mBase + a_row0) * H + a_c * 8;

    const int arow = wid * 16 + (lane & 15);
    const uint32_t arowbase = sbase + arow * 128;
    const uint32_t as0 = (uint32_t)(h ^ (arow & 7));

    const int bk = lane & 15;
    const uint32_t bbase0 = sbase + LBOFF + bk * 32;
    const uint32_t bx0 = (uint32_t)(h ^ ((bk >> 2) & 1));

    __syncthreads();   // B tables ready

    // ---- prologue: stage A chunks 0,1 (hi + lo) ----
    #pragma unroll
    for (int s = 0; s < 2; ++s) {
        const uint32_t so = sbase + s * LSTG;
        #pragma unroll
        for (int j = 0; j < 4; ++j) {
            cpa16(so + a_dst0 + j * 4096,         d_x16 + a_goff + (size_t)32 * j * H + s * BK);
            cpa16(so + 16384 + a_dst0 + j * 4096, d_xlo + a_goff + (size_t)32 * j * H + s * BK);
        }
        CP_COMMIT();
    }

    float c[2][4];
    #pragma unroll
    for (int nt = 0; nt < 2; ++nt)
        #pragma unroll
        for (int q = 0; q < 4; ++q) c[nt][q] = 0.f;

    int stage = 0, pstage = 2;
    for (int kt = 0; kt < NCHUNK; ++kt) {
        CP_WAIT1();
        __syncthreads();

        const uint32_t bofs = stage * LSTG;
        #pragma unroll
        for (int g = 0; g < 4; ++g) {
            uint32_t afh[4], afl[4];
            const uint32_t aslot = (((g << 1) ^ as0) << 4);
            ldsm4(arowbase + bofs + aslot, afh);
            ldsm4(arowbase + bofs + 16384 + aslot, afl);
            const uint32_t bo = (kt * 64 + g * 16) * 32 + (bx0 << 4);
            uint32_t bh[4], bl[4];
            ldsm4t(bbase0 + bo, bh);
            ldsm4t(bbase0 + 32768 + bo, bl);
            mma16816(c[0], afh, bh[0], bh[1]);
            mma16816(c[1], afh, bh[2], bh[3]);
            mma16816(c[0], afh, bl[0], bl[1]);
            mma16816(c[1], afh, bl[2], bl[3]);
            mma16816(c[0], afl, bh[0], bh[1]);
            mma16816(c[1], afl, bh[2], bh[3]);
        }

        const int nc = kt + 2;
        if (nc < NCHUNK) {
            const uint32_t so = sbase + pstage * LSTG;
            #pragma unroll
            for (int j = 0; j < 4; ++j) {
                cpa16(so + a_dst0 + j * 4096,         d_x16 + a_goff + (size_t)32 * j * H + nc * BK);
                cpa16(so + 16384 + a_dst0 + j * 4096, d_xlo + a_goff + (size_t)32 * j * H + nc * BK);
            }
        }
        CP_COMMIT();

        if (++stage == 3)  stage = 0;
        if (++pstage == 3) pstage = 0;
    }

    // ---- store logits ----
    const int r0 = mBase + wid * 16 + (lane >> 2);
    #pragma unroll
    for (int nt = 0; nt < 2; ++nt) {
        float2 v0 = {c[nt][0], c[nt][1]};
        float2 v1 = {c[nt][2], c[nt][3]};
        *(float2*)(d_logits + (size_t)r0 * E + nt * 8 + (lane & 3) * 2) = v0;
        *(float2*)(d_logits + (size_t)(r0 + 8) * E + nt * 8 + (lane & 3) * 2) = v1;
    }
}

// ============================================================
// Top-k router: thread per token; warp-aggregated atomics.
__global__ void __launch_bounds__(256) topk_kernel(const float* __restrict__ rb)
{
    const int t    = blockIdx.x * 256 + threadIdx.x;
    const int lane = threadIdx.x & 31;

    float pv[E];
    {
        const float4* lp = (const float4*)(d_logits + (size_t)t * E);
        #pragma unroll
        for (int j = 0; j < 4; ++j) {
            const float4 v = lp[j];
            pv[j * 4 + 0] = v.x + rb[j * 4 + 0];
            pv[j * 4 + 1] = v.y + rb[j * 4 + 1];
            pv[j * 4 + 2] = v.z + rb[j * 4 + 2];
            pv[j * 4 + 3] = v.w + rb[j * 4 + 3];
        }
    }

    float m = pv[0];
    #pragma unroll
    for (int e = 1; e < E; ++e) m = fmaxf(m, pv[e]);
    float Z = 0.f;
    #pragma unroll
    for (int e = 0; e < E; ++e) { pv[e] = expf(pv[e] - m); Z += pv[e]; }

    int   ids[TOPK];
    float ps [TOPK];
    float ssum = 0.f;
    #pragma unroll
    for (int k = 0; k < TOPK; ++k) {
        int best = 0; float bv = pv[0];
        #pragma unroll
        for (int e = 1; e < E; ++e)
            if (pv[e] > bv) { bv = pv[e]; best = e; }
        ids[k] = best; ps[k] = bv; pv[best] = -1.f; ssum += bv;
    }

    uint32_t mymask = 0;
    #pragma unroll
    for (int k = 0; k < TOPK; ++k) mymask |= (1u << ids[k]);

    #pragma unroll
    for (int e = 0; e < E; ++e) {
        const uint32_t vote = __ballot_sync(0xffffffffu, (mymask >> e) & 1u);
        if (vote) {
            const int leader = __ffs(vote) - 1;
            int base = 0;
            if (lane == leader) base = atomicAdd(&d_counts[e], __popc(vote));
            base = __shfl_sync(0xffffffffu, base, leader);
            if ((mymask >> e) & 1u) {
                const int pos = base + __popc(vote & ((1u << lane) - 1u));
                int kk = 0;
                #pragma unroll
                for (int k = 0; k < TOPK; ++k) if (ids[k] == e) kk = k;
                d_perm_token[e * T + pos] = t;
                d_perm_dest [e * T + pos] = t * TOPK + kk;
                d_perm_coef [e * T + pos] = ps[kk] / ssum;
            }
        }
    }

    const float sn = ssum / Z;
    d_bias[t] = EPSV * sn / (sn + EPSV);
}

// ============================================================
// Grouped GEMM (UNCHANGED from R8): fp16 mma, cp.async 3-stage, BK=64.
__global__ void __launch_bounds__(256, 2) moe_gemm_kernel()
{
    const int e     = blockIdx.z;
    const int cnt   = d_counts[e];
    const int mBase = blockIdx.y * BM;
    if (mBase >= cnt) return;
    const int nBase = blockIdx.x * BN;

    const __half* Wp   = d_w16 + (size_t)e * H * H;
    const int*    ptok = d_perm_token + e * T;

    extern __shared__ char dsm[];
    char* sb = dsm + ((256 - (((uintptr_t)dsm) & 255)) & 255);
    const uint32_t sbase = smem_u32(sb);

    const int tid  = threadIdx.x;
    const int lane = tid & 31;
    const int wid  = tid >> 5;
    const int wm   = wid >> 1;
    const int wn   = wid & 1;

    const int a_row0 = tid >> 3;
    const int a_c    = tid & 7;
    const uint32_t a_dst0 = a_row0 * 128 + ((a_c ^ (a_row0 & 7)) << 4);
    const __half* a_src[4];
    #pragma unroll
    for (int j = 0; j < 4; ++j) {
        const int gm = mBase + a_row0 + 32 * j;
        const int tok = ptok[(gm < cnt) ? gm : (cnt - 1)];
        a_src[j] = d_x16 + (size_t)tok * H + a_c * 8;
    }
    const int b_k0 = tid >> 4;
    const int b_ch = tid & 15;
    const uint32_t b_dst0 = ASTG + b_k0 * 256 + ((b_ch ^ (b_k0 & 7)) << 4);
    const __half* b_src0 = Wp + (size_t)b_k0 * H + nBase + b_ch * 8;

    const int h = lane >> 4;
    uint32_t arowbase[2];
    uint32_t as0[2];
    #pragma unroll
    for (int mt = 0; mt < 2; ++mt) {
        const int row = wm * 32 + mt * 16 + (lane & 15);
        arowbase[mt] = sbase + row * 128;
        as0[mt] = (uint32_t)(h ^ (row & 7));
    }
    uint32_t boff0[4];
    {
        const int k = lane & 15;
        #pragma unroll
        for (int p = 0; p < 4; ++p) {
            const int ch = wn * 8 + p * 2 + h;
            boff0[p] = sbase + ASTG + k * 256 + ((ch ^ (k & 7)) << 4);
        }
    }

    #pragma unroll
    for (int s = 0; s < STAGES - 1; ++s) {
        const uint32_t so = sbase + s * STGB;
        #pragma unroll
        for (int j = 0; j < 4; ++j) {
            cpa16(so + a_dst0 + j * 4096, a_src[j] + s * BK);
            cpa16(so + b_dst0 + j * 4096, b_src0 + (size_t)(16 * j + s * BK) * H);
        }
        CP_COMMIT();
    }

    float c[2][8][4];
    #pragma unroll
    for (int mt = 0; mt < 2; ++mt)
        #pragma unroll
        for (int nt = 0; nt < 8; ++nt)
            #pragma unroll
            for (int q = 0; q < 4; ++q) c[mt][nt][q] = 0.f;

    int stage = 0, pstage = STAGES - 1;
    for (int kt = 0; kt < NCHUNK; ++kt) {
        CP_WAIT1();
        __syncthreads();

        const uint32_t bofs = stage * STGB;

        #pragma unroll
        for (int g = 0; g < 4; ++g) {
            uint32_t afr[2][4];
            #pragma unroll
            for (int mt = 0; mt < 2; ++mt)
                ldsm4(arowbase[mt] + bofs + (((g << 1) ^ as0[mt]) << 4), afr[mt]);
            #pragma unroll
            for (int p = 0; p < 4; ++p) {
                uint32_t bfr[4];
                ldsm4t(boff0[p] + bofs + g * 4096, bfr);
                #pragma unroll
                for (int mt = 0; mt < 2; ++mt) {
                    mma16816(c[mt][p * 2 + 0], afr[mt], bfr[0], bfr[1]);
                    mma16816(c[mt][p * 2 + 1], afr[mt], bfr[2], bfr[3]);
                }
            }
        }

        const int nc = kt + STAGES - 1;
        if (nc < NCHUNK) {
            const uint32_t so = sbase + pstage * STGB;
            #pragma unroll
            for (int j = 0; j < 4; ++j) {
                cpa16(so + a_dst0 + j * 4096, a_src[j] + nc * BK);
                cpa16(so + b_dst0 + j * 4096, b_src0 + (size_t)(16 * j + nc * BK) * H);
            }
        }
        CP_COMMIT();

        if (++stage == STAGES)  stage = 0;
        if (++pstage == STAGES) pstage = 0;
    }

    #pragma unroll
    for (int mt = 0; mt < 2; ++mt) {
        #pragma unroll
        for (int half = 0; half < 2; ++half) {
            const int r  = wm * 32 + mt * 16 + (lane >> 2) + half * 8;
            const int gm = mBase + r;
            if (gm < cnt) {
                const int   dest = d_perm_dest[e * T + gm];
                const float coef = d_perm_coef[e * T + gm];
                __half* orow = d_scratch16 + (size_t)dest * H + nBase;
                #pragma unroll
                for (int nt = 0; nt < 8; ++nt) {
                    const int col = wn * 64 + nt * 8 + (lane & 3) * 2;
                    *(uint32_t*)(orow + col) =
                        pk(c[mt][nt][half * 2 + 0] * coef,
                           c[mt][nt][half * 2 + 1] * coef);
                }
            }
        }
    }
}

// ============================================================
// Reduce (UNCHANGED): out[t] = sum_k scratch16[t*6+k] + bias[t]
__global__ void __launch_bounds__(256) reduce_kernel(float* __restrict__ out)
{
    const int gid = blockIdx.x * blockDim.x + threadIdx.x;
    const int t   = gid >> 7;
    const int c8  = gid & 127;
    const __half* base = d_scratch16 + (size_t)t * TOPK * H + c8 * 8;

    float acc[8];
    #pragma unroll
    for (int j = 0; j < 8; ++j) acc[j] = 0.f;
    #pragma unroll
    for (int k = 0; k < TOPK; ++k) {
        const uint4 v = *(const uint4*)(base + (size_t)k * H);
        const uint32_t w[4] = {v.x, v.y, v.z, v.w};
        #pragma unroll
        for (int j = 0; j < 4; ++j) {
            const float2 f = __half22float2(*(const __half2*)&w[j]);
            acc[j * 2 + 0] += f.x;
            acc[j * 2 + 1] += f.y;
        }
    }
    const float bi = d_bias[t];
    float* op = out + (size_t)t * H + c8 * 8;
    float4 o0, o1;
    o0.x = acc[0] + bi; o0.y = acc[1] + bi; o0.z = acc[2] + bi; o0.w = acc[3] + bi;
    o1.x = acc[4] + bi; o1.y = acc[5] + bi; o1.z = acc[6] + bi; o1.w = acc[7] + bi;
    *(float4*)(op)     = o0;
    *(float4*)(op + 4) = o1;
}

// ============================================================
extern "C" void kernel_launch(void* const* d_in, const int* in_sizes, int n_in,
                              void* d_out, int out_size)
{
    const float* tokens = (const float*)d_in[0];
    const float* rw     = (const float*)d_in[1];
    const float* rb     = (const float*)d_in[2];
    const float* ew     = (const float*)d_in[3];
    float* out = (float*)d_out;

    cudaFuncSetAttribute(moe_gemm_kernel,
                         cudaFuncAttributeMaxDynamicSharedMemorySize, DSMEM);
    cudaFuncSetAttribute(logits_kernel,
                         cudaFuncAttributeMaxDynamicSharedMemorySize, LDSMEM);

    __half* w16p; cudaGetSymbolAddress((void**)&w16p, d_w16);

    cvt_kernel<<<(int)(((size_t)E * H * H) / (256 * 8)), 256>>>(ew, w16p);
    cvtx_kernel<<<(int)(((size_t)T * H) / (256 * 8)), 256>>>(tokens);
    logits_kernel<<<T / 128, 256, LDSMEM>>>(rw);
    topk_kernel<<<T / 256, 256>>>(rb);
    dim3 g(H / BN, T / BM, E);
    moe_gemm_kernel<<<g, 256, DSMEM>>>();
    reduce_kernel<<<(T * H / 8) / 256, 256>>>(out);
}

// round 11
// speedup vs baseline: 4.3098x; 1.0108x over previous
#include <cuda_runtime.h>
#include <cuda_fp16.h>
#include <cstdint>
#include <math.h>

#define H      1024
#define E      16
#define T      8192
#define TOPK   6
#define EPSV   1e-10f

// ---- main GEMM tiling (structure unchanged from R8) ----
#define BM 128
#define BN 128
#define BK 64
#define NCHUNK (H/BK)           // 16
#define STAGES 3
#define ASTG (128*128)          // 16384
#define BSTG (64*256)           // 16384
#define STGB (ASTG+BSTG)        // 32768
#define DSMEM (STAGES*STGB + 256)

// ---- logits mini-GEMM (hi/lo split) + fused topk ----
#define LSTG   32768            // A stage: hi 16KB + lo 16KB
#define LBOFF  (3*LSTG)         // persistent B tables after 3 A stages
#define LTOPK  (LBOFF + 2*32768)       // logits smem [128][17] floats
#define LDSMEM (LTOPK + 128*17*4 + 256)

// ---- device globals (no allocation allowed) ----
__device__ int    d_counts[E];
__device__ int    d_perm_token[E*T];
__device__ int    d_perm_dest [E*T];
__device__ float  d_perm_coef [E*T];
__device__ float  d_bias[T];
__device__ __half d_x16[(size_t)T*H];            // 16 MB (hi)
__device__ __half d_xlo[(size_t)T*H];            // 16 MB (lo residual)
__device__ __half d_w16[(size_t)E*H*H];          // 32 MB
__device__ __half d_scratch16[(size_t)T*TOPK*H]; // 96 MB

// ============================================================
__device__ __forceinline__ uint32_t smem_u32(const void* p) {
    uint32_t a;
    asm("{ .reg .u64 t; cvta.to.shared.u64 t, %1; cvt.u32.u64 %0, t; }"
        : "=r"(a) : "l"(p));
    return a;
}
__device__ __forceinline__ uint32_t pk(float a, float b) {
    __half2 h = __floats2half2_rn(a, b);
    return *(uint32_t*)&h;
}
__device__ __forceinline__ void ldsm4(uint32_t addr, uint32_t* r) {
    asm volatile("ldmatrix.sync.aligned.m8n8.x4.shared.b16 {%0,%1,%2,%3}, [%4];"
        : "=r"(r[0]), "=r"(r[1]), "=r"(r[2]), "=r"(r[3]) : "r"(addr));
}
__device__ __forceinline__ void ldsm4t(uint32_t addr, uint32_t* r) {
    asm volatile("ldmatrix.sync.aligned.m8n8.x4.trans.shared.b16 {%0,%1,%2,%3}, [%4];"
        : "=r"(r[0]), "=r"(r[1]), "=r"(r[2]), "=r"(r[3]) : "r"(addr));
}
__device__ __forceinline__ void mma16816(float* c, const uint32_t* a,
                                         uint32_t b0, uint32_t b1) {
    asm volatile(
        "mma.sync.aligned.m16n8k16.row.col.f32.f16.f16.f32 "
        "{%0,%1,%2,%3}, {%4,%5,%6,%7}, {%8,%9}, {%0,%1,%2,%3};\n"
        : "+f"(c[0]), "+f"(c[1]), "+f"(c[2]), "+f"(c[3])
        : "r"(a[0]), "r"(a[1]), "r"(a[2]), "r"(a[3]), "r"(b0), "r"(b1));
}
__device__ __forceinline__ void cpa16(uint32_t dst, const void* src) {
    asm volatile("cp.async.cg.shared.global [%0], [%1], 16;"
                 :: "r"(dst), "l"(src) : "memory");
}
#define CP_COMMIT() asm volatile("cp.async.commit_group;" ::: "memory")
#define CP_WAIT1()  asm volatile("cp.async.wait_group 1;"  ::: "memory")
#define CP_WAIT2()  asm volatile("cp.async.wait_group 2;"  ::: "memory")

// ============================================================
// Convert W fp32 -> fp16; block 0 also zeroes counts.
__global__ void __launch_bounds__(256) cvt_kernel(const float* __restrict__ src,
                                                  __half* __restrict__ dst) {
    if (blockIdx.x == 0 && threadIdx.x < E) d_counts[threadIdx.x] = 0;
    const size_t i = ((size_t)blockIdx.x * 256 + threadIdx.x) * 8;
    const float4 a = *(const float4*)(src + i);
    const float4 b = *(const float4*)(src + i + 4);
    uint4 u;
    u.x = pk(a.x, a.y); u.y = pk(a.z, a.w);
    u.z = pk(b.x, b.y); u.w = pk(b.z, b.w);
    *(uint4*)(dst + i) = u;
}

// Convert x fp32 -> fp16 hi + lo residual.
__global__ void __launch_bounds__(256) cvtx_kernel(const float* __restrict__ src) {
    const size_t i = ((size_t)blockIdx.x * 256 + threadIdx.x) * 8;
    float v[8];
    *(float4*)(v)     = *(const float4*)(src + i);
    *(float4*)(v + 4) = *(const float4*)(src + i + 4);
    __half hi[8];
    float  lo[8];
    #pragma unroll
    for (int j = 0; j < 8; ++j) {
        hi[j] = __float2half(v[j]);
        lo[j] = v[j] - __half2float(hi[j]);
    }
    *(uint4*)(d_x16 + i) = *(const uint4*)hi;
    uint4 ul;
    ul.x = pk(lo[0], lo[1]); ul.y = pk(lo[2], lo[3]);
    ul.z = pk(lo[4], lo[5]); ul.w = pk(lo[6], lo[7]);
    *(uint4*)(d_xlo + i) = ul;
}

// ============================================================
// Router: logits = xh@wh^T + xh@wl^T + xl@wh^T (fp32-accurate), with
// FUSED softmax/top-k/scatter epilogue. Grid = T/128 CTAs, 256 threads.
__global__ void __launch_bounds__(256) router_kernel(const float* __restrict__ rw,
                                                     const float* __restrict__ rb)
{
    const int mBase = blockIdx.x * 128;

    extern __shared__ char dsm[];
    char* sb = dsm + ((256 - (((uintptr_t)dsm) & 255)) & 255);
    const uint32_t sbase = smem_u32(sb);
    float* larr = (float*)(sb + LTOPK);            // [128][17]

    const int tid  = threadIdx.x;
    const int lane = tid & 31;
    const int wid  = tid >> 5;
    const int h    = lane >> 4;

    // ---- build persistent B tables: wh, wl at [k][e] ----
    {
        const int e = tid >> 4;
        const int kb = (tid & 15) * 4;
        #pragma unroll
        for (int c = 0; c < 16; ++c) {
            const int k = c * 64 + kb;
            const float4 v = *(const float4*)(rw + e * H + k);
            const float vv[4] = {v.x, v.y, v.z, v.w};
            #pragma unroll
            for (int j = 0; j < 4; ++j) {
                const int kk = k + j;
                const uint32_t off = kk * 32
                    + ((((e >> 3) ^ ((kk >> 2) & 1))) << 4) + (e & 7) * 2;
                const __half hh = __float2half(vv[j]);
                const __half hl = __float2half(vv[j] - __half2float(hh));
                *(__half*)(sb + LBOFF + off)         = hh;
                *(__half*)(sb + LBOFF + 32768 + off) = hl;
            }
        }
    }

    // ---- A staging maps (hi + lo per stage) ----
    const int a_row0 = tid >> 3;
    const int a_c    = tid & 7;
    const uint32_t a_dst0 = a_row0 * 128 + ((a_c ^ (a_row0 & 7)) << 4);
    const size_t a_goff = (size_t)(mBase + a_row0) * H + a_c * 8;

    const int arow = wid * 16 + (lane & 15);
    const uint32_t arowbase = sbase + arow * 128;
    const uint32_t as0 = (uint32_t)(h ^ (arow & 7));

    const int bk = lane & 15;
    const uint32_t bbase0 = sbase + LBOFF + bk * 32;
    const uint32_t bx0 = (uint32_t)(h ^ ((bk >> 2) & 1));

    __syncthreads();   // B tables ready

    #pragma unroll
    for (int s = 0; s < 2; ++s) {
        const uint32_t so = sbase + s * LSTG;
        #pragma unroll
        for (int j = 0; j < 4; ++j) {
            cpa16(so + a_dst0 + j * 4096,         d_x16 + a_goff + (size_t)32 * j * H + s * BK);
            cpa16(so + 16384 + a_dst0 + j * 4096, d_xlo + a_goff + (size_t)32 * j * H + s * BK);
        }
        CP_COMMIT();
    }

    float c[2][4];
    #pragma unroll
    for (int nt = 0; nt < 2; ++nt)
        #pragma unroll
        for (int q = 0; q < 4; ++q) c[nt][q] = 0.f;

    int stage = 0, pstage = 2;
    for (int kt = 0; kt < NCHUNK; ++kt) {
        CP_WAIT1();
        __syncthreads();

        // prefetch chunk kt+2 FIRST (overlap LSU with MMAs)
        const int nc = kt + 2;
        if (nc < NCHUNK) {
            const uint32_t so = sbase + pstage * LSTG;
            #pragma unroll
            for (int j = 0; j < 4; ++j) {
                cpa16(so + a_dst0 + j * 4096,         d_x16 + a_goff + (size_t)32 * j * H + nc * BK);
                cpa16(so + 16384 + a_dst0 + j * 4096, d_xlo + a_goff + (size_t)32 * j * H + nc * BK);
            }
        }
        CP_COMMIT();

        const uint32_t bofs = stage * LSTG;
        #pragma unroll
        for (int g = 0; g < 4; ++g) {
            uint32_t afh[4], afl[4];
            const uint32_t aslot = (((g << 1) ^ as0) << 4);
            ldsm4(arowbase + bofs + aslot, afh);
            ldsm4(arowbase + bofs + 16384 + aslot, afl);
            const uint32_t bo = (kt * 64 + g * 16) * 32 + (bx0 << 4);
            uint32_t bh[4], bl[4];
            ldsm4t(bbase0 + bo, bh);
            ldsm4t(bbase0 + 32768 + bo, bl);
            mma16816(c[0], afh, bh[0], bh[1]);
            mma16816(c[1], afh, bh[2], bh[3]);
            mma16816(c[0], afh, bl[0], bl[1]);
            mma16816(c[1], afh, bl[2], bl[3]);
            mma16816(c[0], afl, bh[0], bh[1]);
            mma16816(c[1], afl, bh[2], bh[3]);
        }

        if (++stage == 3)  stage = 0;
        if (++pstage == 3) pstage = 0;
    }

    // ---- stage logits to smem [128][17] ----
    {
        const int r0 = wid * 16 + (lane >> 2);
        #pragma unroll
        for (int nt = 0; nt < 2; ++nt) {
            const int e0 = nt * 8 + (lane & 3) * 2;
            larr[r0 * 17 + e0]           = c[nt][0];
            larr[r0 * 17 + e0 + 1]       = c[nt][1];
            larr[(r0 + 8) * 17 + e0]     = c[nt][2];
            larr[(r0 + 8) * 17 + e0 + 1] = c[nt][3];
        }
    }
    __syncthreads();

    // ---- fused top-k: threads 0..127, one token each ----
    if (tid < 128) {
        const int t = mBase + tid;
        float pv[E];
        #pragma unroll
        for (int e = 0; e < E; ++e) pv[e] = larr[tid * 17 + e] + rb[e];

        float m = pv[0];
        #pragma unroll
        for (int e = 1; e < E; ++e) m = fmaxf(m, pv[e]);
        float Z = 0.f;
        #pragma unroll
        for (int e = 0; e < E; ++e) { pv[e] = expf(pv[e] - m); Z += pv[e]; }

        int   ids[TOPK];
        float ps [TOPK];
        float ssum = 0.f;
        #pragma unroll
        for (int k = 0; k < TOPK; ++k) {
            int best = 0; float bv = pv[0];
            #pragma unroll
            for (int e = 1; e < E; ++e)
                if (pv[e] > bv) { bv = pv[e]; best = e; }
            ids[k] = best; ps[k] = bv; pv[best] = -1.f; ssum += bv;
        }

        uint32_t mymask = 0;
        #pragma unroll
        for (int k = 0; k < TOPK; ++k) mymask |= (1u << ids[k]);

        #pragma unroll
        for (int e = 0; e < E; ++e) {
            const uint32_t vote = __ballot_sync(0xffffffffu, (mymask >> e) & 1u);
            if (vote) {
                const int leader = __ffs(vote) - 1;
                int base = 0;
                if (lane == leader) base = atomicAdd(&d_counts[e], __popc(vote));
                base = __shfl_sync(0xffffffffu, base, leader);
                if ((mymask >> e) & 1u) {
                    const int pos = base + __popc(vote & ((1u << lane) - 1u));
                    int kk = 0;
                    #pragma unroll
                    for (int k = 0; k < TOPK; ++k) if (ids[k] == e) kk = k;
                    d_perm_token[e * T + pos] = t;
                    d_perm_dest [e * T + pos] = t * TOPK + kk;
                    d_perm_coef [e * T + pos] = ps[kk] / ssum;
                }
            }
        }

        const float sn = ssum / Z;
        d_bias[t] = EPSV * sn / (sn + EPSV);
    }
}

// ============================================================
// Grouped GEMM: fp16 mma, cp.async 3-stage, BK=64 (prefetch-first order).
__global__ void __launch_bounds__(256, 2) moe_gemm_kernel()
{
    const int e     = blockIdx.z;
    const int cnt   = d_counts[e];
    const int mBase = blockIdx.y * BM;
    if (mBase >= cnt) return;
    const int nBase = blockIdx.x * BN;

    const __half* Wp   = d_w16 + (size_t)e * H * H;
    const int*    ptok = d_perm_token + e * T;

    extern __shared__ char dsm[];
    char* sb = dsm + ((256 - (((uintptr_t)dsm) & 255)) & 255);
    const uint32_t sbase = smem_u32(sb);

    const int tid  = threadIdx.x;
    const int lane = tid & 31;
    const int wid  = tid >> 5;
    const int wm   = wid >> 1;
    const int wn   = wid & 1;

    const int a_row0 = tid >> 3;
    const int a_c    = tid & 7;
    const uint32_t a_dst0 = a_row0 * 128 + ((a_c ^ (a_row0 & 7)) << 4);
    const __half* a_src[4];
    #pragma unroll
    for (int j = 0; j < 4; ++j) {
        const int gm = mBase + a_row0 + 32 * j;
        const int tok = ptok[(gm < cnt) ? gm : (cnt - 1)];
        a_src[j] = d_x16 + (size_t)tok * H + a_c * 8;
    }
    const int b_k0 = tid >> 4;
    const int b_ch = tid & 15;
    const uint32_t b_dst0 = ASTG + b_k0 * 256 + ((b_ch ^ (b_k0 & 7)) << 4);
    const __half* b_src0 = Wp + (size_t)b_k0 * H + nBase + b_ch * 8;

    const int h = lane >> 4;
    uint32_t arowbase[2];
    uint32_t as0[2];
    #pragma unroll
    for (int mt = 0; mt < 2; ++mt) {
        const int row = wm * 32 + mt * 16 + (lane & 15);
        arowbase[mt] = sbase + row * 128;
        as0[mt] = (uint32_t)(h ^ (row & 7));
    }
    uint32_t boff0[4];
    {
        const int k = lane & 15;
        #pragma unroll
        for (int p = 0; p < 4; ++p) {
            const int ch = wn * 8 + p * 2 + h;
            boff0[p] = sbase + ASTG + k * 256 + ((ch ^ (k & 7)) << 4);
        }
    }

    #pragma unroll
    for (int s = 0; s < STAGES - 1; ++s) {
        const uint32_t so = sbase + s * STGB;
        #pragma unroll
        for (int j = 0; j < 4; ++j) {
            cpa16(so + a_dst0 + j * 4096, a_src[j] + s * BK);
            cpa16(so + b_dst0 + j * 4096, b_src0 + (size_t)(16 * j + s * BK) * H);
        }
        CP_COMMIT();
    }

    float c[2][8][4];
    #pragma unroll
    for (int mt = 0; mt < 2; ++mt)
        #pragma unroll
        for (int nt = 0; nt < 8; ++nt)
            #pragma unroll
            for (int q = 0; q < 4; ++q) c[mt][nt][q] = 0.f;

    int stage = 0, pstage = STAGES - 1;
    for (int kt = 0; kt < NCHUNK; ++kt) {
        CP_WAIT1();
        __syncthreads();

        // prefetch chunk kt+2 FIRST (overlap LSU with MMAs)
        const int nc = kt + STAGES - 1;
        if (nc < NCHUNK) {
            const uint32_t so = sbase + pstage * STGB;
            #pragma unroll
            for (int j = 0; j < 4; ++j) {
                cpa16(so + a_dst0 + j * 4096, a_src[j] + nc * BK);
                cpa16(so + b_dst0 + j * 4096, b_src0 + (size_t)(16 * j + nc * BK) * H);
            }
        }
        CP_COMMIT();

        const uint32_t bofs = stage * STGB;
        #pragma unroll
        for (int g = 0; g < 4; ++g) {
            uint32_t afr[2][4];
            #pragma unroll
            for (int mt = 0; mt < 2; ++mt)
                ldsm4(arowbase[mt] + bofs + (((g << 1) ^ as0[mt]) << 4), afr[mt]);
            #pragma unroll
            for (int p = 0; p < 4; ++p) {
                uint32_t bfr[4];
                ldsm4t(boff0[p] + bofs + g * 4096, bfr);
                #pragma unroll
                for (int mt = 0; mt < 2; ++mt) {
                    mma16816(c[mt][p * 2 + 0], afr[mt], bfr[0], bfr[1]);
                    mma16816(c[mt][p * 2 + 1], afr[mt], bfr[2], bfr[3]);
                }
            }
        }

        if (++stage == STAGES)  stage = 0;
        if (++pstage == STAGES) pstage = 0;
    }

    #pragma unroll
    for (int mt = 0; mt < 2; ++mt) {
        #pragma unroll
        for (int half = 0; half < 2; ++half) {
            const int r  = wm * 32 + mt * 16 + (lane >> 2) + half * 8;
            const int gm = mBase + r;
            if (gm < cnt) {
                const int   dest = d_perm_dest[e * T + gm];
                const float coef = d_perm_coef[e * T + gm];
                __half* orow = d_scratch16 + (size_t)dest * H + nBase;
                #pragma unroll
                for (int nt = 0; nt < 8; ++nt) {
                    const int col = wn * 64 + nt * 8 + (lane & 3) * 2;
                    *(uint32_t*)(orow + col) =
                        pk(c[mt][nt][half * 2 + 0] * coef,
                           c[mt][nt][half * 2 + 1] * coef);
                }
            }
        }
    }
}

// ============================================================
// Reduce: out[t] = sum_k scratch16[t*6+k] + bias[t]   (DRAM roofline)
__global__ void __launch_bounds__(256) reduce_kernel(float* __restrict__ out)
{
    const int gid = blockIdx.x * blockDim.x + threadIdx.x;
    const int t   = gid >> 7;
    const int c8  = gid & 127;
    const __half* base = d_scratch16 + (size_t)t * TOPK * H + c8 * 8;

    float acc[8];
    #pragma unroll
    for (int j = 0; j < 8; ++j) acc[j] = 0.f;
    #pragma unroll
    for (int k = 0; k < TOPK; ++k) {
        const uint4 v = *(const uint4*)(base + (size_t)k * H);
        const uint32_t w[4] = {v.x, v.y, v.z, v.w};
        #pragma unroll
        for (int j = 0; j < 4; ++j) {
            const float2 f = __half22float2(*(const __half2*)&w[j]);
            acc[j * 2 + 0] += f.x;
            acc[j * 2 + 1] += f.y;
        }
    }
    const float bi = d_bias[t];
    float* op = out + (size_t)t * H + c8 * 8;
    float4 o0, o1;
    o0.x = acc[0] + bi; o0.y = acc[1] + bi; o0.z = acc[2] + bi; o0.w = acc[3] + bi;
    o1.x = acc[4] + bi; o1.y = acc[5] + bi; o1.z = acc[6] + bi; o1.w = acc[7] + bi;
    *(float4*)(op)     = o0;
    *(float4*)(op + 4) = o1;
}

// ============================================================
extern "C" void kernel_launch(void* const* d_in, const int* in_sizes, int n_in,
                              void* d_out, int out_size)
{
    const float* tokens = (const float*)d_in[0];
    const float* rw     = (const float*)d_in[1];
    const float* rb     = (const float*)d_in[2];
    const float* ew     = (const float*)d_in[3];
    float* out = (float*)d_out;

    cudaFuncSetAttribute(moe_gemm_kernel,
                         cudaFuncAttributeMaxDynamicSharedMemorySize, DSMEM);
    cudaFuncSetAttribute(router_kernel,
                         cudaFuncAttributeMaxDynamicSharedMemorySize, LDSMEM);

    __half* w16p; cudaGetSymbolAddress((void**)&w16p, d_w16);

    cvt_kernel<<<(int)(((size_t)E * H * H) / (256 * 8)), 256>>>(ew, w16p);
    cvtx_kernel<<<(int)(((size_t)T * H) / (256 * 8)), 256>>>(tokens);
    router_kernel<<<T / 128, 256, LDSMEM>>>(rw, rb);
    dim3 g(H / BN, T / BM, E);
    moe_gemm_kernel<<<g, 256, DSMEM>>>();
    reduce_kernel<<<(T * H / 8) / 256, 256>>>(out);
}

// round 12
// speedup vs baseline: 4.3132x; 1.0008x over previous
#include <cuda_runtime.h>
#include <cuda_fp16.h>
#include <cstdint>
#include <math.h>

#define H      1024
#define E      16
#define T      8192
#define TOPK   6
#define EPSV   1e-10f

// ---- main GEMM: BM=128, BN=128, BK=64; 128 thr, 4 warps (2x2), warptile 64x64
#define BM 128
#define BN 128
#define BK 64
#define NCHUNK (H/BK)           // 16
#define STAGES 3
#define ASTG (128*128)          // 16384
#define BSTG (64*256)           // 16384
#define STGB (ASTG+BSTG)        // 32768
#define DSMEM (STAGES*STGB + 256)

// ---- router mini-GEMM (hi/lo split) + fused topk (unchanged from R11) ----
#define LSTG   32768
#define LBOFF  (3*LSTG)
#define LTOPK  (LBOFF + 2*32768)
#define LDSMEM (LTOPK + 128*17*4 + 256)

// ---- device globals ----
__device__ int    d_counts[E];
__device__ int    d_perm_token[E*T];
__device__ int    d_perm_dest [E*T];
__device__ float  d_perm_coef [E*T];
__device__ float  d_bias[T];
__device__ __half d_x16[(size_t)T*H];
__device__ __half d_xlo[(size_t)T*H];
__device__ __half d_w16[(size_t)E*H*H];
__device__ __half d_scratch16[(size_t)T*TOPK*H];

// ============================================================
__device__ __forceinline__ uint32_t smem_u32(const void* p) {
    uint32_t a;
    asm("{ .reg .u64 t; cvta.to.shared.u64 t, %1; cvt.u32.u64 %0, t; }"
        : "=r"(a) : "l"(p));
    return a;
}
__device__ __forceinline__ uint32_t pk(float a, float b) {
    __half2 h = __floats2half2_rn(a, b);
    return *(uint32_t*)&h;
}
__device__ __forceinline__ void ldsm4(uint32_t addr, uint32_t* r) {
    asm volatile("ldmatrix.sync.aligned.m8n8.x4.shared.b16 {%0,%1,%2,%3}, [%4];"
        : "=r"(r[0]), "=r"(r[1]), "=r"(r[2]), "=r"(r[3]) : "r"(addr));
}
__device__ __forceinline__ void ldsm4t(uint32_t addr, uint32_t* r) {
    asm volatile("ldmatrix.sync.aligned.m8n8.x4.trans.shared.b16 {%0,%1,%2,%3}, [%4];"
        : "=r"(r[0]), "=r"(r[1]), "=r"(r[2]), "=r"(r[3]) : "r"(addr));
}
__device__ __forceinline__ void mma16816(float* c, const uint32_t* a,
                                         uint32_t b0, uint32_t b1) {
    asm volatile(
        "mma.sync.aligned.m16n8k16.row.col.f32.f16.f16.f32 "
        "{%0,%1,%2,%3}, {%4,%5,%6,%7}, {%8,%9}, {%0,%1,%2,%3};\n"
        : "+f"(c[0]), "+f"(c[1]), "+f"(c[2]), "+f"(c[3])
        : "r"(a[0]), "r"(a[1]), "r"(a[2]), "r"(a[3]), "r"(b0), "r"(b1));
}
__device__ __forceinline__ void cpa16(uint32_t dst, const void* src) {
    asm volatile("cp.async.cg.shared.global [%0], [%1], 16;"
                 :: "r"(dst), "l"(src) : "memory");
}
#define CP_COMMIT() asm volatile("cp.async.commit_group;" ::: "memory")
#define CP_WAIT1()  asm volatile("cp.async.wait_group 1;"  ::: "memory")

// ============================================================
__global__ void __launch_bounds__(256) cvt_kernel(const float* __restrict__ src,
                                                  __half* __restrict__ dst) {
    if (blockIdx.x == 0 && threadIdx.x < E) d_counts[threadIdx.x] = 0;
    const size_t i = ((size_t)blockIdx.x * 256 + threadIdx.x) * 8;
    const float4 a = *(const float4*)(src + i);
    const float4 b = *(const float4*)(src + i + 4);
    uint4 u;
    u.x = pk(a.x, a.y); u.y = pk(a.z, a.w);
    u.z = pk(b.x, b.y); u.w = pk(b.z, b.w);
    *(uint4*)(dst + i) = u;
}

__global__ void __launch_bounds__(256) cvtx_kernel(const float* __restrict__ src) {
    const size_t i = ((size_t)blockIdx.x * 256 + threadIdx.x) * 8;
    float v[8];
    *(float4*)(v)     = *(const float4*)(src + i);
    *(float4*)(v + 4) = *(const float4*)(src + i + 4);
    __half hi[8];
    float  lo[8];
    #pragma unroll
    for (int j = 0; j < 8; ++j) {
        hi[j] = __float2half(v[j]);
        lo[j] = v[j] - __half2float(hi[j]);
    }
    *(uint4*)(d_x16 + i) = *(const uint4*)hi;
    uint4 ul;
    ul.x = pk(lo[0], lo[1]); ul.y = pk(lo[2], lo[3]);
    ul.z = pk(lo[4], lo[5]); ul.w = pk(lo[6], lo[7]);
    *(uint4*)(d_xlo + i) = ul;
}

// ============================================================
// Router (UNCHANGED from R11): hi/lo-split logits MMA + fused topk.
__global__ void __launch_bounds__(256) router_kernel(const float* __restrict__ rw,
                                                     const float* __restrict__ rb)
{
    const int mBase = blockIdx.x * 128;

    extern __shared__ char dsm[];
    char* sb = dsm + ((256 - (((uintptr_t)dsm) & 255)) & 255);
    const uint32_t sbase = smem_u32(sb);
    float* larr = (float*)(sb + LTOPK);

    const int tid  = threadIdx.x;
    const int lane = tid & 31;
    const int wid  = tid >> 5;
    const int h    = lane >> 4;

    {
        const int e = tid >> 4;
        const int kb = (tid & 15) * 4;
        #pragma unroll
        for (int c = 0; c < 16; ++c) {
            const int k = c * 64 + kb;
            const float4 v = *(const float4*)(rw + e * H + k);
            const float vv[4] = {v.x, v.y, v.z, v.w};
            #pragma unroll
            for (int j = 0; j < 4; ++j) {
                const int kk = k + j;
                const uint32_t off = kk * 32
                    + ((((e >> 3) ^ ((kk >> 2) & 1))) << 4) + (e & 7) * 2;
                const __half hh = __float2half(vv[j]);
                const __half hl = __float2half(vv[j] - __half2float(hh));
                *(__half*)(sb + LBOFF + off)         = hh;
                *(__half*)(sb + LBOFF + 32768 + off) = hl;
            }
        }
    }

    const int a_row0 = tid >> 3;
    const int a_c    = tid & 7;
    const uint32_t a_dst0 = a_row0 * 128 + ((a_c ^ (a_row0 & 7)) << 4);
    const size_t a_goff = (size_t)(mBase + a_row0) * H + a_c * 8;

    const int arow = wid * 16 + (lane & 15);
    const uint32_t arowbase = sbase + arow * 128;
    const uint32_t as0 = (uint32_t)(h ^ (arow & 7));

    const int bk = lane & 15;
    const uint32_t bbase0 = sbase + LBOFF + bk * 32;
    const uint32_t bx0 = (uint32_t)(h ^ ((bk >> 2) & 1));

    __syncthreads();

    #pragma unroll
    for (int s = 0; s < 2; ++s) {
        const uint32_t so = sbase + s * LSTG;
        #pragma unroll
        for (int j = 0; j < 4; ++j) {
            cpa16(so + a_dst0 + j * 4096,         d_x16 + a_goff + (size_t)32 * j * H + s * BK);
            cpa16(so + 16384 + a_dst0 + j * 4096, d_xlo + a_goff + (size_t)32 * j * H + s * BK);
        }
        CP_COMMIT();
    }

    float c[2][4];
    #pragma unroll
    for (int nt = 0; nt < 2; ++nt)
        #pragma unroll
        for (int q = 0; q < 4; ++q) c[nt][q] = 0.f;

    int stage = 0, pstage = 2;
    for (int kt = 0; kt < NCHUNK; ++kt) {
        CP_WAIT1();
        __syncthreads();

        const int nc = kt + 2;
        if (nc < NCHUNK) {
            const uint32_t so = sbase + pstage * LSTG;
            #pragma unroll
            for (int j = 0; j < 4; ++j) {
                cpa16(so + a_dst0 + j * 4096,         d_x16 + a_goff + (size_t)32 * j * H + nc * BK);
                cpa16(so + 16384 + a_dst0 + j * 4096, d_xlo + a_goff + (size_t)32 * j * H + nc * BK);
            }
        }
        CP_COMMIT();

        const uint32_t bofs = stage * LSTG;
        #pragma unroll
        for (int g = 0; g < 4; ++g) {
            uint32_t afh[4], afl[4];
            const uint32_t aslot = (((g << 1) ^ as0) << 4);
            ldsm4(arowbase + bofs + aslot, afh);
            ldsm4(arowbase + bofs + 16384 + aslot, afl);
            const uint32_t bo = (kt * 64 + g * 16) * 32 + (bx0 << 4);
            uint32_t bh[4], bl[4];
            ldsm4t(bbase0 + bo, bh);
            ldsm4t(bbase0 + 32768 + bo, bl);
            mma16816(c[0], afh, bh[0], bh[1]);
            mma16816(c[1], afh, bh[2], bh[3]);
            mma16816(c[0], afh, bl[0], bl[1]);
            mma16816(c[1], afh, bl[2], bl[3]);
            mma16816(c[0], afl, bh[0], bh[1]);
            mma16816(c[1], afl, bh[2], bh[3]);
        }

        if (++stage == 3)  stage = 0;
        if (++pstage == 3) pstage = 0;
    }

    {
        const int r0 = wid * 16 + (lane >> 2);
        #pragma unroll
        for (int nt = 0; nt < 2; ++nt) {
            const int e0 = nt * 8 + (lane & 3) * 2;
            larr[r0 * 17 + e0]           = c[nt][0];
            larr[r0 * 17 + e0 + 1]       = c[nt][1];
            larr[(r0 + 8) * 17 + e0]     = c[nt][2];
            larr[(r0 + 8) * 17 + e0 + 1] = c[nt][3];
        }
    }
    __syncthreads();

    if (tid < 128) {
        const int t = mBase + tid;
        float pv[E];
        #pragma unroll
        for (int e = 0; e < E; ++e) pv[e] = larr[tid * 17 + e] + rb[e];

        float m = pv[0];
        #pragma unroll
        for (int e = 1; e < E; ++e) m = fmaxf(m, pv[e]);
        float Z = 0.f;
        #pragma unroll
        for (int e = 0; e < E; ++e) { pv[e] = expf(pv[e] - m); Z += pv[e]; }

        int   ids[TOPK];
        float ps [TOPK];
        float ssum = 0.f;
        #pragma unroll
        for (int k = 0; k < TOPK; ++k) {
            int best = 0; float bv = pv[0];
            #pragma unroll
            for (int e = 1; e < E; ++e)
                if (pv[e] > bv) { bv = pv[e]; best = e; }
            ids[k] = best; ps[k] = bv; pv[best] = -1.f; ssum += bv;
        }

        uint32_t mymask = 0;
        #pragma unroll
        for (int k = 0; k < TOPK; ++k) mymask |= (1u << ids[k]);

        #pragma unroll
        for (int e = 0; e < E; ++e) {
            const uint32_t vote = __ballot_sync(0xffffffffu, (mymask >> e) & 1u);
            if (vote) {
                const int leader = __ffs(vote) - 1;
                int base = 0;
                if (lane == leader) base = atomicAdd(&d_counts[e], __popc(vote));
                base = __shfl_sync(0xffffffffu, base, leader);
                if ((mymask >> e) & 1u) {
                    const int pos = base + __popc(vote & ((1u << lane) - 1u));
                    int kk = 0;
                    #pragma unroll
                    for (int k = 0; k < TOPK; ++k) if (ids[k] == e) kk = k;
                    d_perm_token[e * T + pos] = t;
                    d_perm_dest [e * T + pos] = t * TOPK + kk;
                    d_perm_coef [e * T + pos] = ps[kk] / ssum;
                }
            }
        }

        const float sn = ssum / Z;
        d_bias[t] = EPSV * sn / (sn + EPSV);
    }
}

// ============================================================
// Grouped GEMM: 128 threads, 4 warps (2x2), warptile 64x64.
// Halves smem fragment traffic per MAC (crossbar was co-saturated).
__global__ void __launch_bounds__(128, 2) moe_gemm_kernel()
{
    const int e     = blockIdx.z;
    const int cnt   = d_counts[e];
    const int mBase = blockIdx.y * BM;
    if (mBase >= cnt) return;
    const int nBase = blockIdx.x * BN;

    const __half* Wp   = d_w16 + (size_t)e * H * H;
    const int*    ptok = d_perm_token + e * T;

    extern __shared__ char dsm[];
    char* sb = dsm + ((256 - (((uintptr_t)dsm) & 255)) & 255);
    const uint32_t sbase = smem_u32(sb);

    const int tid  = threadIdx.x;
    const int lane = tid & 31;
    const int wid  = tid >> 5;
    const int wm   = wid >> 1;      // 0..1 -> rows wm*64
    const int wn   = wid & 1;       // 0..1 -> cols wn*64

    // ---- cp.async maps: 8 A + 8 B 16B chunks per thread per k-chunk ----
    // A: row = (tid>>3) + 16j  (row&7 invariant); dst advances +2048j
    const int a_row0 = tid >> 3;               // 0..15
    const int a_c    = tid & 7;
    const uint32_t a_dst0 = a_row0 * 128 + ((a_c ^ (a_row0 & 7)) << 4);
    uint32_t a_off[8];                          // halfword offsets into d_x16
    #pragma unroll
    for (int j = 0; j < 8; ++j) {
        const int gm = mBase + a_row0 + 16 * j;
        const int tok = ptok[(gm < cnt) ? gm : (cnt - 1)];
        a_off[j] = (uint32_t)(tok * H + a_c * 8);
    }
    // B: k = (tid>>4) + 8j (k&7 invariant); dst advances +2048j
    const int b_k0 = tid >> 4;                 // 0..7
    const int b_ch = tid & 15;
    const uint32_t b_dst0 = ASTG + b_k0 * 256 + ((b_ch ^ (b_k0 & 7)) << 4);
    const __half* b_src0 = Wp + (size_t)b_k0 * H + nBase + b_ch * 8;

    // ---- fragment addresses ----
    const int h = lane >> 4;
    const uint32_t as0 = (uint32_t)(h ^ (lane & 7));           // mt-invariant
    const uint32_t arowbase0 = sbase + (wm * 64 + (lane & 15)) * 128;  // + mt*2048
    uint32_t boff0[4];
    {
        const int k = lane & 15;
        #pragma unroll
        for (int p = 0; p < 4; ++p) {
            const int ch = wn * 8 + p * 2 + h;
            boff0[p] = sbase + ASTG + k * 256 + ((ch ^ (k & 7)) << 4);  // + g*4096
        }
    }

    // ---- prologue: stage chunks 0,1 ----
    #pragma unroll
    for (int s = 0; s < STAGES - 1; ++s) {
        const uint32_t so = sbase + s * STGB;
        #pragma unroll
        for (int j = 0; j < 8; ++j) {
            cpa16(so + a_dst0 + j * 2048, d_x16 + a_off[j] + s * BK);
            cpa16(so + b_dst0 + j * 2048, b_src0 + (size_t)(8 * j + s * BK) * H);
        }
        CP_COMMIT();
    }

    float c[4][8][4];
    #pragma unroll
    for (int mt = 0; mt < 4; ++mt)
        #pragma unroll
        for (int nt = 0; nt < 8; ++nt)
            #pragma unroll
            for (int q = 0; q < 4; ++q) c[mt][nt][q] = 0.f;

    int stage = 0, pstage = STAGES - 1;
    for (int kt = 0; kt < NCHUNK; ++kt) {
        CP_WAIT1();
        __syncthreads();

        // prefetch chunk kt+2 first
        const int nc = kt + STAGES - 1;
        if (nc < NCHUNK) {
            const uint32_t so = sbase + pstage * STGB;
            #pragma unroll
            for (int j = 0; j < 8; ++j) {
                cpa16(so + a_dst0 + j * 2048, d_x16 + a_off[j] + nc * BK);
                cpa16(so + b_dst0 + j * 2048, b_src0 + (size_t)(8 * j + nc * BK) * H);
            }
        }
        CP_COMMIT();

        const uint32_t bofs = stage * STGB;
        #pragma unroll
        for (int g = 0; g < 4; ++g) {
            uint32_t afr[4][4];
            const uint32_t aslot = (((g << 1) ^ as0) << 4);
            #pragma unroll
            for (int mt = 0; mt < 4; ++mt)
                ldsm4(arowbase0 + mt * 2048 + bofs + aslot, afr[mt]);
            #pragma unroll
            for (int p = 0; p < 4; ++p) {
                uint32_t bfr[4];
                ldsm4t(boff0[p] + bofs + g * 4096, bfr);
                #pragma unroll
                for (int mt = 0; mt < 4; ++mt) {
                    mma16816(c[mt][p * 2 + 0], afr[mt], bfr[0], bfr[1]);
                    mma16816(c[mt][p * 2 + 1], afr[mt], bfr[2], bfr[3]);
                }
            }
        }

        if (++stage == STAGES)  stage = 0;
        if (++pstage == STAGES) pstage = 0;
    }

    // ---- epilogue: scale by coef, store fp16 rows to scratch ----
    #pragma unroll
    for (int mt = 0; mt < 4; ++mt) {
        #pragma unroll
        for (int half = 0; half < 2; ++half) {
            const int r  = wm * 64 + mt * 16 + (lane >> 2) + half * 8;
            const int gm = mBase + r;
            if (gm < cnt) {
                const int   dest = d_perm_dest[e * T + gm];
                const float coef = d_perm_coef[e * T + gm];
                __half* orow = d_scratch16 + (size_t)dest * H + nBase;
                #pragma unroll
                for (int nt = 0; nt < 8; ++nt) {
                    const int col = wn * 64 + nt * 8 + (lane & 3) * 2;
                    *(uint32_t*)(orow + col) =
                        pk(c[mt][nt][half * 2 + 0] * coef,
                           c[mt][nt][half * 2 + 1] * coef);
                }
            }
        }
    }
}

// ============================================================
__global__ void __launch_bounds__(256) reduce_kernel(float* __restrict__ out)
{
    const int gid = blockIdx.x * blockDim.x + threadIdx.x;
    const int t   = gid >> 7;
    const int c8  = gid & 127;
    const __half* base = d_scratch16 + (size_t)t * TOPK * H + c8 * 8;

    float acc[8];
    #pragma unroll
    for (int j = 0; j < 8; ++j) acc[j] = 0.f;
    #pragma unroll
    for (int k = 0; k < TOPK; ++k) {
        const uint4 v = *(const uint4*)(base + (size_t)k * H);
        const uint32_t w[4] = {v.x, v.y, v.z, v.w};
        #pragma unroll
        for (int j = 0; j < 4; ++j) {
            const float2 f = __half22float2(*(const __half2*)&w[j]);
            acc[j * 2 + 0] += f.x;
            acc[j * 2 + 1] += f.y;
        }
    }
    const float bi = d_bias[t];
    float* op = out + (size_t)t * H + c8 * 8;
    float4 o0, o1;
    o0.x = acc[0] + bi; o0.y = acc[1] + bi; o0.z = acc[2] + bi; o0.w = acc[3] + bi;
    o1.x = acc[4] + bi; o1.y = acc[5] + bi; o1.z = acc[6] + bi; o1.w = acc[7] + bi;
    *(float4*)(op)     = o0;
    *(float4*)(op + 4) = o1;
}

// ============================================================
extern "C" void kernel_launch(void* const* d_in, const int* in_sizes, int n_in,
                              void* d_out, int out_size)
{
    const float* tokens = (const float*)d_in[0];
    const float* rw     = (const float*)d_in[1];
    const float* rb     = (const float*)d_in[2];
    const float* ew     = (const float*)d_in[3];
    float* out = (float*)d_out;

    cudaFuncSetAttribute(moe_gemm_kernel,
                         cudaFuncAttributeMaxDynamicSharedMemorySize, DSMEM);
    cudaFuncSetAttribute(router_kernel,
                         cudaFuncAttributeMaxDynamicSharedMemorySize, LDSMEM);

    __half* w16p; cudaGetSymbolAddress((void**)&w16p, d_w16);

    cvt_kernel<<<(int)(((size_t)E * H * H) / (256 * 8)), 256>>>(ew, w16p);
    cvtx_kernel<<<(int)(((size_t)T * H) / (256 * 8)), 256>>>(tokens);
    router_kernel<<<T / 128, 256, LDSMEM>>>(rw, rb);
    dim3 g(H / BN, T / BM, E);
    moe_gemm_kernel<<<g, 128, DSMEM>>>();
    reduce_kernel<<<(T * H / 8) / 256, 256>>>(out);
}